// round 6
// baseline (speedup 1.0000x reference)
#include <cuda_runtime.h>
#include <math.h>

#define N_NODES 100000
#define N_EDGES 3200000
#define IN_CH   602
#define HID     16
#define OUT_CH  41

#define M_TILE   256
#define K_CHUNK  32
#define SCAN_BLK 1024
#define NB_SCAN  ((N_NODES + SCAN_BLK - 1) / SCAN_BLK)   // 98

// Scratch (device globals; no allocation allowed)
__device__ float g_h1   [N_NODES * HID];
__device__ float g_r    [N_NODES * HID];
__device__ float g_mean2[N_NODES * HID];
__device__ int   g_deg  [N_NODES];
__device__ int   g_excl [N_NODES];
__device__ int   g_blksum[128];
__device__ int   g_rowptr[N_NODES + 1];
__device__ int   g_cursor[N_NODES];
__device__ int   g_csr  [N_EDGES];

// ---------------------------------------------------------------------------
// K1: h1[N,16] = x[N,602] @ W1[602,16].
// 128 threads; thread = 8 strided rows x 4 cols.  xs bytes cross the smem
// crossbar 4x (vs 8x in the 8x2 scheme).  xs reads: scalar, stride-1 across
// lanes (conflict-free, proven).  ws read: single broadcast float4.
// ---------------------------------------------------------------------------
__global__ __launch_bounds__(128)
void gemm1_kernel(const float* __restrict__ x,
                  const float* __restrict__ W1,
                  float* __restrict__ h1) {
    __shared__ float xs[K_CHUNK][M_TILE + 1];
    __shared__ float ws[K_CHUNK][HID];

    const int tid      = threadIdx.x;
    const int row_base = blockIdx.x * M_TILE;
    const int tr = tid & 31;         // row lane (rows tr + 32*i)
    const int cg = (tid >> 5) * 4;   // column group: 0,4,8,12

    float acc[8][4];
    #pragma unroll
    for (int i = 0; i < 8; i++)
        #pragma unroll
        for (int j = 0; j < 4; j++) acc[i][j] = 0.f;

    #pragma unroll 1
    for (int kc = 0; kc < IN_CH; kc += K_CHUNK) {
        // stage x tile: 256 rows x 32 k = 8192 elems by 128 threads
        #pragma unroll 8
        for (int i = 0; i < 64; i++) {
            int g = i * 128 + tid;
            int r = g >> 5;
            int k = g & 31;
            int gk = kc + k;
            float v = 0.f;
            if (gk < IN_CH) {
                int grow = row_base + r;
                int cr = (grow < N_NODES) ? grow : 0;   // clamp; never stored
                v = __ldg(x + (size_t)cr * IN_CH + gk);
            }
            xs[k][r] = v;
        }
        // stage W chunk: 32 x 16 = 512 elems by 128 threads
        #pragma unroll
        for (int i = 0; i < 4; i++) {
            int g = i * 128 + tid;
            int k = g >> 4;
            int c = g & 15;
            int gk = kc + k;
            ws[k][c] = (gk < IN_CH) ? W1[(size_t)gk * HID + c] : 0.f;
        }
        __syncthreads();

        #pragma unroll
        for (int k = 0; k < K_CHUNK; k++) {
            float4 wv = *(const float4*)&ws[k][cg];   // warp-broadcast (1 addr)
            #pragma unroll
            for (int i = 0; i < 8; i++) {
                float xv = xs[k][tr + 32 * i];        // conflict-free
                acc[i][0] += xv * wv.x;
                acc[i][1] += xv * wv.y;
                acc[i][2] += xv * wv.z;
                acc[i][3] += xv * wv.w;
            }
        }
        __syncthreads();
    }

    #pragma unroll
    for (int i = 0; i < 8; i++) {
        int row = row_base + tr + 32 * i;
        if (row < N_NODES) {
            float4 v = make_float4(acc[i][0], acc[i][1], acc[i][2], acc[i][3]);
            *(float4*)(h1 + (size_t)row * 16 + cg) = v;
        }
    }
}

// ---------------------------------------------------------------------------
// CSR construction  (proven path)
// ---------------------------------------------------------------------------
__global__ void deg_kernel(const int* __restrict__ dst, int* __restrict__ deg) {
    int e = blockIdx.x * blockDim.x + threadIdx.x;
    if (e < N_EDGES) atomicAdd(&deg[dst[e]], 1);
}

__global__ __launch_bounds__(SCAN_BLK)
void scan1_kernel(const int* __restrict__ deg,
                  int* __restrict__ excl,
                  int* __restrict__ blksum) {
    __shared__ int wsum[32];
    int tid = threadIdx.x, lane = tid & 31, wid = tid >> 5;
    int i = blockIdx.x * SCAN_BLK + tid;
    int v = (i < N_NODES) ? deg[i] : 0;
    int x = v;
    #pragma unroll
    for (int d = 1; d < 32; d <<= 1) {
        int t = __shfl_up_sync(0xffffffffu, x, d);
        if (lane >= d) x += t;
    }
    if (lane == 31) wsum[wid] = x;
    __syncthreads();
    if (wid == 0) {
        int s = wsum[lane];
        #pragma unroll
        for (int d = 1; d < 32; d <<= 1) {
            int t = __shfl_up_sync(0xffffffffu, s, d);
            if (lane >= d) s += t;
        }
        wsum[lane] = s;
    }
    __syncthreads();
    int woff = (wid == 0) ? 0 : wsum[wid - 1];
    if (i < N_NODES) excl[i] = woff + x - v;
    if (tid == SCAN_BLK - 1) blksum[blockIdx.x] = wsum[31];
}

__global__ __launch_bounds__(128)
void scan2_kernel(int* __restrict__ blksum) {
    __shared__ int ws[4];
    int tid = threadIdx.x, lane = tid & 31, wid = tid >> 5;
    int v = (tid < NB_SCAN) ? blksum[tid] : 0;
    int x = v;
    #pragma unroll
    for (int d = 1; d < 32; d <<= 1) {
        int t = __shfl_up_sync(0xffffffffu, x, d);
        if (lane >= d) x += t;
    }
    if (lane == 31) ws[wid] = x;
    __syncthreads();
    int woff = 0;
    #pragma unroll
    for (int w = 0; w < 4; w++) if (w < wid) woff += ws[w];
    if (tid < NB_SCAN) blksum[tid] = woff + x - v;
}

__global__ void scan3_kernel(const int* __restrict__ excl,
                             const int* __restrict__ blksum,
                             int* __restrict__ rowptr,
                             int* __restrict__ cursor) {
    int i = blockIdx.x * blockDim.x + threadIdx.x;
    if (i >= N_NODES) return;
    int v = excl[i] + blksum[i / SCAN_BLK];
    rowptr[i] = v;
    cursor[i] = v;
    if (i == 0) rowptr[N_NODES] = N_EDGES;
}

__global__ void fill_kernel(const int* __restrict__ src,
                            const int* __restrict__ dst,
                            int* __restrict__ cursor,
                            int* __restrict__ csr_src) {
    int e = blockIdx.x * blockDim.x + threadIdx.x;
    if (e >= N_EDGES) return;
    int slot = atomicAdd(&cursor[dst[e]], 1);
    csr_src[slot] = src[e];
}

// ---------------------------------------------------------------------------
// Gather layer: 16 threads per node (lane = channel).  out = mean of in-nbrs.
// ---------------------------------------------------------------------------
template <bool RELU>
__global__ void gather_kernel(const float* __restrict__ h,
                              const int* __restrict__ rowptr,
                              const int* __restrict__ csr_src,
                              const float* __restrict__ bias,
                              float* __restrict__ out) {
    int t = blockIdx.x * blockDim.x + threadIdx.x;
    int nid = t >> 4;
    int c   = t & 15;
    if (nid >= N_NODES) return;
    int beg = rowptr[nid];
    int end = rowptr[nid + 1];
    float s = 0.f;
    int j = beg;
    for (; j + 4 <= end; j += 4) {
        int s0 = csr_src[j], s1 = csr_src[j + 1],
            s2 = csr_src[j + 2], s3 = csr_src[j + 3];
        float v0 = h[(size_t)s0 * 16 + c];
        float v1 = h[(size_t)s1 * 16 + c];
        float v2 = h[(size_t)s2 * 16 + c];
        float v3 = h[(size_t)s3 * 16 + c];
        s += v0 + v1 + v2 + v3;
    }
    for (; j < end; j++) s += h[(size_t)csr_src[j] * 16 + c];
    float inv = 1.f / fmaxf((float)(end - beg), 1.f);
    float m = s * inv;
    if (RELU) m = fmaxf(m + bias[c], 0.f);
    out[(size_t)nid * 16 + c] = m;
}

// ---------------------------------------------------------------------------
// K5: out = log_softmax( mean2 @ W2 + b2 ).  Thread per node.
// ---------------------------------------------------------------------------
__global__ void out_kernel(const float* __restrict__ W2,
                           const float* __restrict__ b2,
                           const float* __restrict__ mean2,
                           float* __restrict__ out) {
    __shared__ float w2s[HID * OUT_CH];
    __shared__ float b2s[OUT_CH];
    for (int i = threadIdx.x; i < HID * OUT_CH; i += blockDim.x) w2s[i] = W2[i];
    for (int i = threadIdx.x; i < OUT_CH;       i += blockDim.x) b2s[i] = b2[i];
    __syncthreads();

    int n = blockIdx.x * blockDim.x + threadIdx.x;
    if (n >= N_NODES) return;

    const float4* av = (const float4*)(mean2 + (size_t)n * 16);
    float4 m0 = av[0], m1 = av[1], m2 = av[2], m3 = av[3];
    float m[16] = { m0.x, m0.y, m0.z, m0.w, m1.x, m1.y, m1.z, m1.w,
                    m2.x, m2.y, m2.z, m2.w, m3.x, m3.y, m3.z, m3.w };

    float o[OUT_CH];
    #pragma unroll
    for (int j = 0; j < OUT_CH; j++) {
        float s = b2s[j];
        #pragma unroll
        for (int k = 0; k < HID; k++)
            s += m[k] * w2s[k * OUT_CH + j];
        o[j] = s;
    }

    float mx = o[0];
    #pragma unroll
    for (int j = 1; j < OUT_CH; j++) mx = fmaxf(mx, o[j]);
    float sum = 0.0f;
    #pragma unroll
    for (int j = 0; j < OUT_CH; j++) sum += __expf(o[j] - mx);
    float ls = __logf(sum) + mx;

    float* op = out + (size_t)n * OUT_CH;
    #pragma unroll
    for (int j = 0; j < OUT_CH; j++) op[j] = o[j] - ls;
}

// ---------------------------------------------------------------------------
extern "C" void kernel_launch(void* const* d_in, const int* in_sizes, int n_in,
                              void* d_out, int out_size) {
    const float* x  = (const float*)d_in[0];
    const int*   ei = (const int*)  d_in[1];
    const float* W1 = (const float*)d_in[2];
    const float* b1 = (const float*)d_in[3];
    const float* W2 = (const float*)d_in[4];
    const float* b2 = (const float*)d_in[5];
    float* out = (float*)d_out;

    const int* src = ei;
    const int* dst = ei + N_EDGES;

    float *p_h1, *p_r, *p_mean2;
    int *p_deg, *p_excl, *p_blksum, *p_rowptr, *p_cursor, *p_csr;
    cudaGetSymbolAddress((void**)&p_h1,     g_h1);
    cudaGetSymbolAddress((void**)&p_r,      g_r);
    cudaGetSymbolAddress((void**)&p_mean2,  g_mean2);
    cudaGetSymbolAddress((void**)&p_deg,    g_deg);
    cudaGetSymbolAddress((void**)&p_excl,   g_excl);
    cudaGetSymbolAddress((void**)&p_blksum, g_blksum);
    cudaGetSymbolAddress((void**)&p_rowptr, g_rowptr);
    cudaGetSymbolAddress((void**)&p_cursor, g_cursor);
    cudaGetSymbolAddress((void**)&p_csr,    g_csr);

    cudaMemsetAsync(p_deg, 0, sizeof(int) * N_NODES);

    // CSR build: histogram -> exclusive scan -> slot fill
    deg_kernel <<<(N_EDGES + 255) / 256, 256>>>(dst, p_deg);
    scan1_kernel<<<NB_SCAN, SCAN_BLK>>>(p_deg, p_excl, p_blksum);
    scan2_kernel<<<1, 128>>>(p_blksum);
    scan3_kernel<<<(N_NODES + 255) / 256, 256>>>(p_excl, p_blksum, p_rowptr, p_cursor);
    fill_kernel <<<(N_EDGES + 255) / 256, 256>>>(src, dst, p_cursor, p_csr);

    // K1: h1 = x @ W1  (8 rows x 4 cols per thread, 128-thread blocks)
    gemm1_kernel<<<(N_NODES + M_TILE - 1) / M_TILE, 128>>>(x, W1, p_h1);

    // Layer 1 aggregate: r = relu(mean_nbr(h1) + b1)
    gather_kernel<true> <<<(N_NODES * 16 + 255) / 256, 256>>>(p_h1, p_rowptr, p_csr, b1, p_r);

    // Layer 2 aggregate: mean2 = mean_nbr(r)   (W2 applied after, by linearity)
    gather_kernel<false><<<(N_NODES * 16 + 255) / 256, 256>>>(p_r, p_rowptr, p_csr, b1, p_mean2);

    // K5: out = log_softmax(mean2 @ W2 + b2)
    out_kernel<<<(N_NODES + 255) / 256, 256>>>(W2, b2, p_mean2, out);
}

// round 7
// speedup vs baseline: 1.3708x; 1.3708x over previous
#include <cuda_runtime.h>
#include <math.h>

#define N_NODES 100000
#define N_EDGES 3200000
#define IN_CH   602
#define HID     16
#define OUT_CH  41

#define M_TILE   256
#define KC       16
#define NCH      ((IN_CH + KC - 1) / KC)   // 38
#define XS_STR   (M_TILE + 2)              // 258: conflict-free STS + LDS
#define SCAN_BLK 1024
#define NB_SCAN  ((N_NODES + SCAN_BLK - 1) / SCAN_BLK)   // 98

// Scratch (device globals; no allocation allowed)
__device__ float g_h1   [N_NODES * HID];
__device__ float g_r    [N_NODES * HID];
__device__ float g_mean2[N_NODES * HID];
__device__ int   g_deg  [N_NODES];
__device__ int   g_excl [N_NODES];
__device__ int   g_blksum[128];
__device__ int   g_rowptr[N_NODES + 1];
__device__ int   g_cursor[N_NODES];
__device__ int   g_csr  [N_EDGES];

// ---------------------------------------------------------------------------
// K1: h1[N,16] = x[N,602] @ W1[602,16].
// Double-buffered pipeline: prefetch next K-chunk (float2 LDG) into registers
// while computing current chunk from smem.  Inner loop = proven 8x2 scheme.
// ---------------------------------------------------------------------------
__global__ __launch_bounds__(256)
void gemm1_kernel(const float* __restrict__ x,
                  const float* __restrict__ W1,
                  float* __restrict__ h1) {
    __shared__ float xs[KC][XS_STR];
    __shared__ float ws[KC][HID];

    const int tid      = threadIdx.x;
    const int row_base = blockIdx.x * M_TILE;
    const int tr = tid & 31;         // compute: row lane (rows tr + 32*i)
    const int tc = (tid >> 5) * 2;   // compute: column pair

    // prefetch mapping: thread covers rows {pr + 32*i}, k-pair pk within chunk
    const int pr = tid >> 3;         // 0..31
    const int pk = (tid & 7) * 2;    // 0,2,...,14
    const int wk = tid >> 4;         // W: k row 0..15
    const int wc = tid & 15;         // W: col

    float2 px[8];
    float  pw;

    float acc[8][2];
    #pragma unroll
    for (int i = 0; i < 8; i++) { acc[i][0] = 0.f; acc[i][1] = 0.f; }

    // ---- prefetch chunk 0 ----
    {
        const int kc = 0;
        #pragma unroll
        for (int i = 0; i < 8; i++) {
            int r = i * 32 + pr;
            int grow = row_base + r;
            int cr = (grow < N_NODES) ? grow : 0;
            int gk = kc + pk;
            float2 v = make_float2(0.f, 0.f);
            if (gk + 1 < IN_CH) v = *(const float2*)(x + (size_t)cr * IN_CH + gk);
            px[i] = v;
        }
        pw = (kc + wk < IN_CH) ? W1[(size_t)(kc + wk) * HID + wc] : 0.f;
    }

    #pragma unroll 1
    for (int c = 0; c < NCH; c++) {
        // store staged chunk
        #pragma unroll
        for (int i = 0; i < 8; i++) {
            xs[pk    ][i * 32 + pr] = px[i].x;
            xs[pk + 1][i * 32 + pr] = px[i].y;
        }
        ws[wk][wc] = pw;
        __syncthreads();

        // prefetch chunk c+1 (LDGs overlap the compute below)
        if (c + 1 < NCH) {
            const int kc = (c + 1) * KC;
            #pragma unroll
            for (int i = 0; i < 8; i++) {
                int r = i * 32 + pr;
                int grow = row_base + r;
                int cr = (grow < N_NODES) ? grow : 0;
                int gk = kc + pk;
                float2 v = make_float2(0.f, 0.f);
                if (gk + 1 < IN_CH) v = *(const float2*)(x + (size_t)cr * IN_CH + gk);
                px[i] = v;
            }
            pw = (kc + wk < IN_CH) ? W1[(size_t)(kc + wk) * HID + wc] : 0.f;
        }

        // compute current chunk
        #pragma unroll
        for (int k = 0; k < KC; k++) {
            float w0 = ws[k][tc];
            float w1 = ws[k][tc + 1];
            #pragma unroll
            for (int i = 0; i < 8; i++) {
                float xv = xs[k][tr + 32 * i];
                acc[i][0] += xv * w0;
                acc[i][1] += xv * w1;
            }
        }
        __syncthreads();
    }

    #pragma unroll
    for (int i = 0; i < 8; i++) {
        int row = row_base + tr + 32 * i;
        if (row < N_NODES) {
            float2 v = make_float2(acc[i][0], acc[i][1]);
            *(float2*)(h1 + (size_t)row * 16 + tc) = v;
        }
    }
}

// ---------------------------------------------------------------------------
// CSR construction  (proven path)
// ---------------------------------------------------------------------------
__global__ void deg_kernel(const int* __restrict__ dst, int* __restrict__ deg) {
    int e = blockIdx.x * blockDim.x + threadIdx.x;
    if (e < N_EDGES) atomicAdd(&deg[dst[e]], 1);
}

__global__ __launch_bounds__(SCAN_BLK)
void scan1_kernel(const int* __restrict__ deg,
                  int* __restrict__ excl,
                  int* __restrict__ blksum) {
    __shared__ int wsum[32];
    int tid = threadIdx.x, lane = tid & 31, wid = tid >> 5;
    int i = blockIdx.x * SCAN_BLK + tid;
    int v = (i < N_NODES) ? deg[i] : 0;
    int x = v;
    #pragma unroll
    for (int d = 1; d < 32; d <<= 1) {
        int t = __shfl_up_sync(0xffffffffu, x, d);
        if (lane >= d) x += t;
    }
    if (lane == 31) wsum[wid] = x;
    __syncthreads();
    if (wid == 0) {
        int s = wsum[lane];
        #pragma unroll
        for (int d = 1; d < 32; d <<= 1) {
            int t = __shfl_up_sync(0xffffffffu, s, d);
            if (lane >= d) s += t;
        }
        wsum[lane] = s;
    }
    __syncthreads();
    int woff = (wid == 0) ? 0 : wsum[wid - 1];
    if (i < N_NODES) excl[i] = woff + x - v;
    if (tid == SCAN_BLK - 1) blksum[blockIdx.x] = wsum[31];
}

__global__ __launch_bounds__(128)
void scan2_kernel(int* __restrict__ blksum) {
    __shared__ int ws[4];
    int tid = threadIdx.x, lane = tid & 31, wid = tid >> 5;
    int v = (tid < NB_SCAN) ? blksum[tid] : 0;
    int x = v;
    #pragma unroll
    for (int d = 1; d < 32; d <<= 1) {
        int t = __shfl_up_sync(0xffffffffu, x, d);
        if (lane >= d) x += t;
    }
    if (lane == 31) ws[wid] = x;
    __syncthreads();
    int woff = 0;
    #pragma unroll
    for (int w = 0; w < 4; w++) if (w < wid) woff += ws[w];
    if (tid < NB_SCAN) blksum[tid] = woff + x - v;
}

__global__ void scan3_kernel(const int* __restrict__ excl,
                             const int* __restrict__ blksum,
                             int* __restrict__ rowptr,
                             int* __restrict__ cursor) {
    int i = blockIdx.x * blockDim.x + threadIdx.x;
    if (i >= N_NODES) return;
    int v = excl[i] + blksum[i / SCAN_BLK];
    rowptr[i] = v;
    cursor[i] = v;
    if (i == 0) rowptr[N_NODES] = N_EDGES;
}

__global__ void fill_kernel(const int* __restrict__ src,
                            const int* __restrict__ dst,
                            int* __restrict__ cursor,
                            int* __restrict__ csr_src) {
    int e = blockIdx.x * blockDim.x + threadIdx.x;
    if (e >= N_EDGES) return;
    int slot = atomicAdd(&cursor[dst[e]], 1);
    csr_src[slot] = src[e];
}

// ---------------------------------------------------------------------------
// Gather layer: 16 threads per node (lane = channel).  out = mean of in-nbrs.
// ---------------------------------------------------------------------------
template <bool RELU>
__global__ void gather_kernel(const float* __restrict__ h,
                              const int* __restrict__ rowptr,
                              const int* __restrict__ csr_src,
                              const float* __restrict__ bias,
                              float* __restrict__ out) {
    int t = blockIdx.x * blockDim.x + threadIdx.x;
    int nid = t >> 4;
    int c   = t & 15;
    if (nid >= N_NODES) return;
    int beg = rowptr[nid];
    int end = rowptr[nid + 1];
    float s = 0.f;
    int j = beg;
    for (; j + 4 <= end; j += 4) {
        int s0 = csr_src[j], s1 = csr_src[j + 1],
            s2 = csr_src[j + 2], s3 = csr_src[j + 3];
        float v0 = h[(size_t)s0 * 16 + c];
        float v1 = h[(size_t)s1 * 16 + c];
        float v2 = h[(size_t)s2 * 16 + c];
        float v3 = h[(size_t)s3 * 16 + c];
        s += v0 + v1 + v2 + v3;
    }
    for (; j < end; j++) s += h[(size_t)csr_src[j] * 16 + c];
    float inv = 1.f / fmaxf((float)(end - beg), 1.f);
    float m = s * inv;
    if (RELU) m = fmaxf(m + bias[c], 0.f);
    out[(size_t)nid * 16 + c] = m;
}

// ---------------------------------------------------------------------------
// K5: out = log_softmax( mean2 @ W2 + b2 ).  Thread per node.
// ---------------------------------------------------------------------------
__global__ void out_kernel(const float* __restrict__ W2,
                           const float* __restrict__ b2,
                           const float* __restrict__ mean2,
                           float* __restrict__ out) {
    __shared__ float w2s[HID * OUT_CH];
    __shared__ float b2s[OUT_CH];
    for (int i = threadIdx.x; i < HID * OUT_CH; i += blockDim.x) w2s[i] = W2[i];
    for (int i = threadIdx.x; i < OUT_CH;       i += blockDim.x) b2s[i] = b2[i];
    __syncthreads();

    int n = blockIdx.x * blockDim.x + threadIdx.x;
    if (n >= N_NODES) return;

    const float4* av = (const float4*)(mean2 + (size_t)n * 16);
    float4 m0 = av[0], m1 = av[1], m2 = av[2], m3 = av[3];
    float m[16] = { m0.x, m0.y, m0.z, m0.w, m1.x, m1.y, m1.z, m1.w,
                    m2.x, m2.y, m2.z, m2.w, m3.x, m3.y, m3.z, m3.w };

    float o[OUT_CH];
    #pragma unroll
    for (int j = 0; j < OUT_CH; j++) {
        float s = b2s[j];
        #pragma unroll
        for (int k = 0; k < HID; k++)
            s += m[k] * w2s[k * OUT_CH + j];
        o[j] = s;
    }

    float mx = o[0];
    #pragma unroll
    for (int j = 1; j < OUT_CH; j++) mx = fmaxf(mx, o[j]);
    float sum = 0.0f;
    #pragma unroll
    for (int j = 0; j < OUT_CH; j++) sum += __expf(o[j] - mx);
    float ls = __logf(sum) + mx;

    float* op = out + (size_t)n * OUT_CH;
    #pragma unroll
    for (int j = 0; j < OUT_CH; j++) op[j] = o[j] - ls;
}

// ---------------------------------------------------------------------------
extern "C" void kernel_launch(void* const* d_in, const int* in_sizes, int n_in,
                              void* d_out, int out_size) {
    const float* x  = (const float*)d_in[0];
    const int*   ei = (const int*)  d_in[1];
    const float* W1 = (const float*)d_in[2];
    const float* b1 = (const float*)d_in[3];
    const float* W2 = (const float*)d_in[4];
    const float* b2 = (const float*)d_in[5];
    float* out = (float*)d_out;

    const int* src = ei;
    const int* dst = ei + N_EDGES;

    float *p_h1, *p_r, *p_mean2;
    int *p_deg, *p_excl, *p_blksum, *p_rowptr, *p_cursor, *p_csr;
    cudaGetSymbolAddress((void**)&p_h1,     g_h1);
    cudaGetSymbolAddress((void**)&p_r,      g_r);
    cudaGetSymbolAddress((void**)&p_mean2,  g_mean2);
    cudaGetSymbolAddress((void**)&p_deg,    g_deg);
    cudaGetSymbolAddress((void**)&p_excl,   g_excl);
    cudaGetSymbolAddress((void**)&p_blksum, g_blksum);
    cudaGetSymbolAddress((void**)&p_rowptr, g_rowptr);
    cudaGetSymbolAddress((void**)&p_cursor, g_cursor);
    cudaGetSymbolAddress((void**)&p_csr,    g_csr);

    cudaMemsetAsync(p_deg, 0, sizeof(int) * N_NODES);

    // CSR build: histogram -> exclusive scan -> slot fill
    deg_kernel <<<(N_EDGES + 255) / 256, 256>>>(dst, p_deg);
    scan1_kernel<<<NB_SCAN, SCAN_BLK>>>(p_deg, p_excl, p_blksum);
    scan2_kernel<<<1, 128>>>(p_blksum);
    scan3_kernel<<<(N_NODES + 255) / 256, 256>>>(p_excl, p_blksum, p_rowptr, p_cursor);
    fill_kernel <<<(N_EDGES + 255) / 256, 256>>>(src, dst, p_cursor, p_csr);

    // K1: h1 = x @ W1  (double-buffered 8x2)
    gemm1_kernel<<<(N_NODES + M_TILE - 1) / M_TILE, 256>>>(x, W1, p_h1);

    // Layer 1 aggregate: r = relu(mean_nbr(h1) + b1)
    gather_kernel<true> <<<(N_NODES * 16 + 255) / 256, 256>>>(p_h1, p_rowptr, p_csr, b1, p_r);

    // Layer 2 aggregate: mean2 = mean_nbr(r)   (W2 applied after, by linearity)
    gather_kernel<false><<<(N_NODES * 16 + 255) / 256, 256>>>(p_r, p_rowptr, p_csr, b1, p_mean2);

    // K5: out = log_softmax(mean2 @ W2 + b2)
    out_kernel<<<(N_NODES + 255) / 256, 256>>>(W2, b2, p_mean2, out);
}

// round 8
// speedup vs baseline: 1.5454x; 1.1274x over previous
#include <cuda_runtime.h>
#include <math.h>

#define N_NODES 100000
#define N_EDGES 3200000
#define IN_CH   602
#define HID     16
#define OUT_CH  41

#define M_TILE   256
#define KC       16
#define NCH      ((IN_CH + KC - 1) / KC)   // 38
#define XS_STR   (M_TILE + 2)              // 258: conflict-free STS + LDS
#define SCAN_BLK 1024
#define NB_SCAN  ((N_NODES + SCAN_BLK - 1) / SCAN_BLK)   // 98

// Scratch (device globals; no allocation allowed)
__device__ float g_h1   [N_NODES * HID];
__device__ float g_r    [N_NODES * HID];
__device__ float g_mean2[N_NODES * HID];
__device__ int   g_deg  [N_NODES];
__device__ int   g_excl [N_NODES];
__device__ int   g_blksum[128];
__device__ int   g_rowptr[N_NODES + 1];
__device__ int   g_cursor[N_NODES];
__device__ int   g_csr  [N_EDGES];

// ---------------------------------------------------------------------------
// K1: h1[N,16] = x[N,602] @ W1[602,16].
// Double-buffered pipeline (proven, 138us): prefetch next K-chunk (float2 LDG)
// into registers while computing current chunk from smem.  8x2 inner scheme.
// ---------------------------------------------------------------------------
__global__ __launch_bounds__(256)
void gemm1_kernel(const float* __restrict__ x,
                  const float* __restrict__ W1,
                  float* __restrict__ h1) {
    __shared__ float xs[KC][XS_STR];
    __shared__ float ws[KC][HID];

    const int tid      = threadIdx.x;
    const int row_base = blockIdx.x * M_TILE;
    const int tr = tid & 31;         // compute: row lane (rows tr + 32*i)
    const int tc = (tid >> 5) * 2;   // compute: column pair

    const int pr = tid >> 3;         // prefetch row lane 0..31
    const int pk = (tid & 7) * 2;    // prefetch k-pair 0,2,...,14
    const int wk = tid >> 4;         // W: k row 0..15
    const int wc = tid & 15;         // W: col

    float2 px[8];
    float  pw;

    float acc[8][2];
    #pragma unroll
    for (int i = 0; i < 8; i++) { acc[i][0] = 0.f; acc[i][1] = 0.f; }

    // ---- prefetch chunk 0 ----
    {
        const int kc = 0;
        #pragma unroll
        for (int i = 0; i < 8; i++) {
            int r = i * 32 + pr;
            int grow = row_base + r;
            int cr = (grow < N_NODES) ? grow : 0;
            int gk = kc + pk;
            float2 v = make_float2(0.f, 0.f);
            if (gk + 1 < IN_CH) v = *(const float2*)(x + (size_t)cr * IN_CH + gk);
            px[i] = v;
        }
        pw = (kc + wk < IN_CH) ? W1[(size_t)(kc + wk) * HID + wc] : 0.f;
    }

    #pragma unroll 1
    for (int c = 0; c < NCH; c++) {
        #pragma unroll
        for (int i = 0; i < 8; i++) {
            xs[pk    ][i * 32 + pr] = px[i].x;
            xs[pk + 1][i * 32 + pr] = px[i].y;
        }
        ws[wk][wc] = pw;
        __syncthreads();

        if (c + 1 < NCH) {
            const int kc = (c + 1) * KC;
            #pragma unroll
            for (int i = 0; i < 8; i++) {
                int r = i * 32 + pr;
                int grow = row_base + r;
                int cr = (grow < N_NODES) ? grow : 0;
                int gk = kc + pk;
                float2 v = make_float2(0.f, 0.f);
                if (gk + 1 < IN_CH) v = *(const float2*)(x + (size_t)cr * IN_CH + gk);
                px[i] = v;
            }
            pw = (kc + wk < IN_CH) ? W1[(size_t)(kc + wk) * HID + wc] : 0.f;
        }

        #pragma unroll
        for (int k = 0; k < KC; k++) {
            float w0 = ws[k][tc];
            float w1 = ws[k][tc + 1];
            #pragma unroll
            for (int i = 0; i < 8; i++) {
                float xv = xs[k][tr + 32 * i];
                acc[i][0] += xv * w0;
                acc[i][1] += xv * w1;
            }
        }
        __syncthreads();
    }

    #pragma unroll
    for (int i = 0; i < 8; i++) {
        int row = row_base + tr + 32 * i;
        if (row < N_NODES) {
            float2 v = make_float2(acc[i][0], acc[i][1]);
            *(float2*)(h1 + (size_t)row * 16 + tc) = v;
        }
    }
}

// ---------------------------------------------------------------------------
// CSR construction  (proven path)
// ---------------------------------------------------------------------------
__global__ void deg_kernel(const int* __restrict__ dst, int* __restrict__ deg) {
    int e = blockIdx.x * blockDim.x + threadIdx.x;
    if (e < N_EDGES) atomicAdd(&deg[dst[e]], 1);
}

__global__ __launch_bounds__(SCAN_BLK)
void scan1_kernel(const int* __restrict__ deg,
                  int* __restrict__ excl,
                  int* __restrict__ blksum) {
    __shared__ int wsum[32];
    int tid = threadIdx.x, lane = tid & 31, wid = tid >> 5;
    int i = blockIdx.x * SCAN_BLK + tid;
    int v = (i < N_NODES) ? deg[i] : 0;
    int x = v;
    #pragma unroll
    for (int d = 1; d < 32; d <<= 1) {
        int t = __shfl_up_sync(0xffffffffu, x, d);
        if (lane >= d) x += t;
    }
    if (lane == 31) wsum[wid] = x;
    __syncthreads();
    if (wid == 0) {
        int s = wsum[lane];
        #pragma unroll
        for (int d = 1; d < 32; d <<= 1) {
            int t = __shfl_up_sync(0xffffffffu, s, d);
            if (lane >= d) s += t;
        }
        wsum[lane] = s;
    }
    __syncthreads();
    int woff = (wid == 0) ? 0 : wsum[wid - 1];
    if (i < N_NODES) excl[i] = woff + x - v;
    if (tid == SCAN_BLK - 1) blksum[blockIdx.x] = wsum[31];
}

__global__ __launch_bounds__(128)
void scan2_kernel(int* __restrict__ blksum) {
    __shared__ int ws[4];
    int tid = threadIdx.x, lane = tid & 31, wid = tid >> 5;
    int v = (tid < NB_SCAN) ? blksum[tid] : 0;
    int x = v;
    #pragma unroll
    for (int d = 1; d < 32; d <<= 1) {
        int t = __shfl_up_sync(0xffffffffu, x, d);
        if (lane >= d) x += t;
    }
    if (lane == 31) ws[wid] = x;
    __syncthreads();
    int woff = 0;
    #pragma unroll
    for (int w = 0; w < 4; w++) if (w < wid) woff += ws[w];
    if (tid < NB_SCAN) blksum[tid] = woff + x - v;
}

__global__ void scan3_kernel(const int* __restrict__ excl,
                             const int* __restrict__ blksum,
                             int* __restrict__ rowptr,
                             int* __restrict__ cursor) {
    int i = blockIdx.x * blockDim.x + threadIdx.x;
    if (i >= N_NODES) return;
    int v = excl[i] + blksum[i / SCAN_BLK];
    rowptr[i] = v;
    cursor[i] = v;
    if (i == 0) rowptr[N_NODES] = N_EDGES;
}

__global__ void fill_kernel(const int* __restrict__ src,
                            const int* __restrict__ dst,
                            int* __restrict__ cursor,
                            int* __restrict__ csr_src) {
    int e = blockIdx.x * blockDim.x + threadIdx.x;
    if (e >= N_EDGES) return;
    int slot = atomicAdd(&cursor[dst[e]], 1);
    csr_src[slot] = src[e];
}

// ---------------------------------------------------------------------------
// Gather layer: 16 threads per node (lane = channel).  out = mean of in-nbrs.
// ---------------------------------------------------------------------------
template <bool RELU>
__global__ void gather_kernel(const float* __restrict__ h,
                              const int* __restrict__ rowptr,
                              const int* __restrict__ csr_src,
                              const float* __restrict__ bias,
                              float* __restrict__ out) {
    int t = blockIdx.x * blockDim.x + threadIdx.x;
    int nid = t >> 4;
    int c   = t & 15;
    if (nid >= N_NODES) return;
    int beg = rowptr[nid];
    int end = rowptr[nid + 1];
    float s = 0.f;
    int j = beg;
    for (; j + 4 <= end; j += 4) {
        int s0 = csr_src[j], s1 = csr_src[j + 1],
            s2 = csr_src[j + 2], s3 = csr_src[j + 3];
        float v0 = h[(size_t)s0 * 16 + c];
        float v1 = h[(size_t)s1 * 16 + c];
        float v2 = h[(size_t)s2 * 16 + c];
        float v3 = h[(size_t)s3 * 16 + c];
        s += v0 + v1 + v2 + v3;
    }
    for (; j < end; j++) s += h[(size_t)csr_src[j] * 16 + c];
    float inv = 1.f / fmaxf((float)(end - beg), 1.f);
    float m = s * inv;
    if (RELU) m = fmaxf(m + bias[c], 0.f);
    out[(size_t)nid * 16 + c] = m;
}

// ---------------------------------------------------------------------------
// K5: out = log_softmax( mean2 @ W2 + b2 ).  Thread per node.
// ---------------------------------------------------------------------------
__global__ void out_kernel(const float* __restrict__ W2,
                           const float* __restrict__ b2,
                           const float* __restrict__ mean2,
                           float* __restrict__ out) {
    __shared__ float w2s[HID * OUT_CH];
    __shared__ float b2s[OUT_CH];
    for (int i = threadIdx.x; i < HID * OUT_CH; i += blockDim.x) w2s[i] = W2[i];
    for (int i = threadIdx.x; i < OUT_CH;       i += blockDim.x) b2s[i] = b2[i];
    __syncthreads();

    int n = blockIdx.x * blockDim.x + threadIdx.x;
    if (n >= N_NODES) return;

    const float4* av = (const float4*)(mean2 + (size_t)n * 16);
    float4 m0 = av[0], m1 = av[1], m2 = av[2], m3 = av[3];
    float m[16] = { m0.x, m0.y, m0.z, m0.w, m1.x, m1.y, m1.z, m1.w,
                    m2.x, m2.y, m2.z, m2.w, m3.x, m3.y, m3.z, m3.w };

    float o[OUT_CH];
    #pragma unroll
    for (int j = 0; j < OUT_CH; j++) {
        float s = b2s[j];
        #pragma unroll
        for (int k = 0; k < HID; k++)
            s += m[k] * w2s[k * OUT_CH + j];
        o[j] = s;
    }

    float mx = o[0];
    #pragma unroll
    for (int j = 1; j < OUT_CH; j++) mx = fmaxf(mx, o[j]);
    float sum = 0.0f;
    #pragma unroll
    for (int j = 0; j < OUT_CH; j++) sum += __expf(o[j] - mx);
    float ls = __logf(sum) + mx;

    float* op = out + (size_t)n * OUT_CH;
    #pragma unroll
    for (int j = 0; j < OUT_CH; j++) op[j] = o[j] - ls;
}

// ---------------------------------------------------------------------------
extern "C" void kernel_launch(void* const* d_in, const int* in_sizes, int n_in,
                              void* d_out, int out_size) {
    const float* x  = (const float*)d_in[0];
    const int*   ei = (const int*)  d_in[1];
    const float* W1 = (const float*)d_in[2];
    const float* b1 = (const float*)d_in[3];
    const float* W2 = (const float*)d_in[4];
    const float* b2 = (const float*)d_in[5];
    float* out = (float*)d_out;

    const int* src = ei;
    const int* dst = ei + N_EDGES;

    float *p_h1, *p_r, *p_mean2;
    int *p_deg, *p_excl, *p_blksum, *p_rowptr, *p_cursor, *p_csr;
    cudaGetSymbolAddress((void**)&p_h1,     g_h1);
    cudaGetSymbolAddress((void**)&p_r,      g_r);
    cudaGetSymbolAddress((void**)&p_mean2,  g_mean2);
    cudaGetSymbolAddress((void**)&p_deg,    g_deg);
    cudaGetSymbolAddress((void**)&p_excl,   g_excl);
    cudaGetSymbolAddress((void**)&p_blksum, g_blksum);
    cudaGetSymbolAddress((void**)&p_rowptr, g_rowptr);
    cudaGetSymbolAddress((void**)&p_cursor, g_cursor);
    cudaGetSymbolAddress((void**)&p_csr,    g_csr);

    // Side stream + fork/join events (created on first call, which is the
    // uncaptured correctness run; reused identically during graph capture).
    static cudaStream_t s_csr = nullptr;
    static cudaEvent_t  ev_fork = nullptr, ev_join = nullptr;
    if (s_csr == nullptr) {
        cudaStreamCreateWithFlags(&s_csr, cudaStreamNonBlocking);
        cudaEventCreateWithFlags(&ev_fork, cudaEventDisableTiming);
        cudaEventCreateWithFlags(&ev_join, cudaEventDisableTiming);
    }

    // Fork: CSR chain on side stream, gemm on main stream — independent.
    cudaEventRecord(ev_fork, 0);
    cudaStreamWaitEvent(s_csr, ev_fork, 0);

    cudaMemsetAsync(p_deg, 0, sizeof(int) * N_NODES, s_csr);
    deg_kernel <<<(N_EDGES + 255) / 256, 256, 0, s_csr>>>(dst, p_deg);
    scan1_kernel<<<NB_SCAN, SCAN_BLK, 0, s_csr>>>(p_deg, p_excl, p_blksum);
    scan2_kernel<<<1, 128, 0, s_csr>>>(p_blksum);
    scan3_kernel<<<(N_NODES + 255) / 256, 256, 0, s_csr>>>(p_excl, p_blksum, p_rowptr, p_cursor);
    fill_kernel <<<(N_EDGES + 255) / 256, 256, 0, s_csr>>>(src, dst, p_cursor, p_csr);
    cudaEventRecord(ev_join, s_csr);

    // K1 on main stream, overlapped with CSR build
    gemm1_kernel<<<(N_NODES + M_TILE - 1) / M_TILE, 256>>>(x, W1, p_h1);

    // Join: gather1 needs both h1 and the CSR
    cudaStreamWaitEvent(0, ev_join, 0);

    gather_kernel<true> <<<(N_NODES * 16 + 255) / 256, 256>>>(p_h1, p_rowptr, p_csr, b1, p_r);
    gather_kernel<false><<<(N_NODES * 16 + 255) / 256, 256>>>(p_r, p_rowptr, p_csr, b1, p_mean2);
    out_kernel<<<(N_NODES + 255) / 256, 256>>>(W2, b2, p_mean2, out);
}

// round 9
// speedup vs baseline: 1.6022x; 1.0367x over previous
#include <cuda_runtime.h>
#include <math.h>

#define N_NODES 100000
#define N_EDGES 3200000
#define IN_CH   602
#define HID     16
#define OUT_CH  41

#define M_TILE   256
#define KC       16
#define XS_ROW   (KC + 4)                  // 20 floats: conflict-free LDS.128, 16B-aligned rows
#define NCH      ((IN_CH + KC - 1) / KC)   // 38
#define SCAN_BLK 1024
#define NB_SCAN  ((N_NODES + SCAN_BLK - 1) / SCAN_BLK)   // 98

// Scratch (device globals; no allocation allowed)
__device__ float g_h1   [N_NODES * HID];
__device__ float g_r    [N_NODES * HID];
__device__ float g_mean2[N_NODES * HID];
__device__ int   g_deg  [N_NODES];
__device__ int   g_excl [N_NODES];
__device__ int   g_blksum[128];
__device__ int   g_rowptr[N_NODES + 1];
__device__ int   g_cursor[N_NODES];
__device__ int   g_csr  [N_EDGES];

// ---------------------------------------------------------------------------
// K1: h1[N,16] = x[N,602] @ W1[602,16].
// Double-buffered prefetch (proven) + row-major xs so the inner loop reads
// x via LDS.128 (4 k at once).  Row stride 20 floats: conflict-free.
// ---------------------------------------------------------------------------
__global__ __launch_bounds__(256)
void gemm1_kernel(const float* __restrict__ x,
                  const float* __restrict__ W1,
                  float* __restrict__ h1) {
    __shared__ float xs[M_TILE][XS_ROW];
    __shared__ float ws[KC][HID];

    const int tid      = threadIdx.x;
    const int row_base = blockIdx.x * M_TILE;
    const int tr = tid & 31;         // compute: row lane (rows tr + 32*i)
    const int tc = (tid >> 5) * 2;   // compute: column pair

    const int pr = tid >> 3;         // prefetch row lane 0..31
    const int pk = (tid & 7) * 2;    // prefetch k-pair 0,2,...,14
    const int wk = tid >> 4;         // W: k row 0..15
    const int wc = tid & 15;         // W: col

    float2 px[8];
    float  pw;

    float acc[8][2];
    #pragma unroll
    for (int i = 0; i < 8; i++) { acc[i][0] = 0.f; acc[i][1] = 0.f; }

    // ---- prefetch chunk 0 ----
    {
        const int kc = 0;
        #pragma unroll
        for (int i = 0; i < 8; i++) {
            int r = i * 32 + pr;
            int grow = row_base + r;
            int cr = (grow < N_NODES) ? grow : 0;
            int gk = kc + pk;
            float2 v = make_float2(0.f, 0.f);
            if (gk + 1 < IN_CH) v = *(const float2*)(x + (size_t)cr * IN_CH + gk);
            px[i] = v;
        }
        pw = (kc + wk < IN_CH) ? W1[(size_t)(kc + wk) * HID + wc] : 0.f;
    }

    #pragma unroll 1
    for (int c = 0; c < NCH; c++) {
        // store staged chunk (STS.64, 8B-aligned, conflict-free)
        #pragma unroll
        for (int i = 0; i < 8; i++) {
            *(float2*)&xs[i * 32 + pr][pk] = px[i];
        }
        ws[wk][wc] = pw;
        __syncthreads();

        // prefetch chunk c+1 (LDGs overlap the compute below)
        if (c + 1 < NCH) {
            const int kc = (c + 1) * KC;
            #pragma unroll
            for (int i = 0; i < 8; i++) {
                int r = i * 32 + pr;
                int grow = row_base + r;
                int cr = (grow < N_NODES) ? grow : 0;
                int gk = kc + pk;
                float2 v = make_float2(0.f, 0.f);
                if (gk + 1 < IN_CH) v = *(const float2*)(x + (size_t)cr * IN_CH + gk);
                px[i] = v;
            }
            pw = (kc + wk < IN_CH) ? W1[(size_t)(kc + wk) * HID + wc] : 0.f;
        }

        // compute current chunk: LDS.128 over k
        #pragma unroll
        for (int k0 = 0; k0 < KC; k0 += 4) {
            float4 xv[8];
            #pragma unroll
            for (int i = 0; i < 8; i++)
                xv[i] = *(const float4*)&xs[tr + 32 * i][k0];
            #pragma unroll
            for (int kk = 0; kk < 4; kk++) {
                float w0 = ws[k0 + kk][tc];
                float w1 = ws[k0 + kk][tc + 1];
                #pragma unroll
                for (int i = 0; i < 8; i++) {
                    float xvk = (kk == 0) ? xv[i].x : (kk == 1) ? xv[i].y
                              : (kk == 2) ? xv[i].z : xv[i].w;
                    acc[i][0] += xvk * w0;
                    acc[i][1] += xvk * w1;
                }
            }
        }
        __syncthreads();
    }

    #pragma unroll
    for (int i = 0; i < 8; i++) {
        int row = row_base + tr + 32 * i;
        if (row < N_NODES) {
            float2 v = make_float2(acc[i][0], acc[i][1]);
            *(float2*)(h1 + (size_t)row * 16 + tc) = v;
        }
    }
}

// ---------------------------------------------------------------------------
// CSR construction  (proven path)
// ---------------------------------------------------------------------------
__global__ void deg_kernel(const int* __restrict__ dst, int* __restrict__ deg) {
    int e = blockIdx.x * blockDim.x + threadIdx.x;
    if (e < N_EDGES) atomicAdd(&deg[dst[e]], 1);
}

__global__ __launch_bounds__(SCAN_BLK)
void scan1_kernel(const int* __restrict__ deg,
                  int* __restrict__ excl,
                  int* __restrict__ blksum) {
    __shared__ int wsum[32];
    int tid = threadIdx.x, lane = tid & 31, wid = tid >> 5;
    int i = blockIdx.x * SCAN_BLK + tid;
    int v = (i < N_NODES) ? deg[i] : 0;
    int x = v;
    #pragma unroll
    for (int d = 1; d < 32; d <<= 1) {
        int t = __shfl_up_sync(0xffffffffu, x, d);
        if (lane >= d) x += t;
    }
    if (lane == 31) wsum[wid] = x;
    __syncthreads();
    if (wid == 0) {
        int s = wsum[lane];
        #pragma unroll
        for (int d = 1; d < 32; d <<= 1) {
            int t = __shfl_up_sync(0xffffffffu, s, d);
            if (lane >= d) s += t;
        }
        wsum[lane] = s;
    }
    __syncthreads();
    int woff = (wid == 0) ? 0 : wsum[wid - 1];
    if (i < N_NODES) excl[i] = woff + x - v;
    if (tid == SCAN_BLK - 1) blksum[blockIdx.x] = wsum[31];
}

__global__ __launch_bounds__(128)
void scan2_kernel(int* __restrict__ blksum) {
    __shared__ int ws[4];
    int tid = threadIdx.x, lane = tid & 31, wid = tid >> 5;
    int v = (tid < NB_SCAN) ? blksum[tid] : 0;
    int x = v;
    #pragma unroll
    for (int d = 1; d < 32; d <<= 1) {
        int t = __shfl_up_sync(0xffffffffu, x, d);
        if (lane >= d) x += t;
    }
    if (lane == 31) ws[wid] = x;
    __syncthreads();
    int woff = 0;
    #pragma unroll
    for (int w = 0; w < 4; w++) if (w < wid) woff += ws[w];
    if (tid < NB_SCAN) blksum[tid] = woff + x - v;
}

__global__ void scan3_kernel(const int* __restrict__ excl,
                             const int* __restrict__ blksum,
                             int* __restrict__ rowptr,
                             int* __restrict__ cursor) {
    int i = blockIdx.x * blockDim.x + threadIdx.x;
    if (i >= N_NODES) return;
    int v = excl[i] + blksum[i / SCAN_BLK];
    rowptr[i] = v;
    cursor[i] = v;
    if (i == 0) rowptr[N_NODES] = N_EDGES;
}

__global__ void fill_kernel(const int* __restrict__ src,
                            const int* __restrict__ dst,
                            int* __restrict__ cursor,
                            int* __restrict__ csr_src) {
    int e = blockIdx.x * blockDim.x + threadIdx.x;
    if (e >= N_EDGES) return;
    int slot = atomicAdd(&cursor[dst[e]], 1);
    csr_src[slot] = src[e];
}

// ---------------------------------------------------------------------------
// Gather layer: 4 threads per node (lane = 4-channel group, float4 loads).
// out = mean of in-neighbors; RELU variant adds bias + relu.
// ---------------------------------------------------------------------------
template <bool RELU>
__global__ void gather_kernel(const float* __restrict__ h,
                              const int* __restrict__ rowptr,
                              const int* __restrict__ csr_src,
                              const float* __restrict__ bias,
                              float* __restrict__ out) {
    int t = blockIdx.x * blockDim.x + threadIdx.x;
    int nid = t >> 2;
    int c4  = t & 3;
    if (nid >= N_NODES) return;
    int beg = rowptr[nid];
    int end = rowptr[nid + 1];
    const float4* hv = (const float4*)h;
    float4 s = make_float4(0.f, 0.f, 0.f, 0.f);
    int j = beg;
    for (; j + 4 <= end; j += 4) {
        int s0 = csr_src[j], s1 = csr_src[j + 1],
            s2 = csr_src[j + 2], s3 = csr_src[j + 3];
        float4 v0 = hv[(size_t)s0 * 4 + c4];
        float4 v1 = hv[(size_t)s1 * 4 + c4];
        float4 v2 = hv[(size_t)s2 * 4 + c4];
        float4 v3 = hv[(size_t)s3 * 4 + c4];
        s.x += (v0.x + v1.x) + (v2.x + v3.x);
        s.y += (v0.y + v1.y) + (v2.y + v3.y);
        s.z += (v0.z + v1.z) + (v2.z + v3.z);
        s.w += (v0.w + v1.w) + (v2.w + v3.w);
    }
    for (; j < end; j++) {
        float4 v = hv[(size_t)csr_src[j] * 4 + c4];
        s.x += v.x; s.y += v.y; s.z += v.z; s.w += v.w;
    }
    float inv = 1.f / fmaxf((float)(end - beg), 1.f);
    float4 m;
    m.x = s.x * inv; m.y = s.y * inv; m.z = s.z * inv; m.w = s.w * inv;
    if (RELU) {
        float4 bb = __ldg(((const float4*)bias) + c4);
        m.x = fmaxf(m.x + bb.x, 0.f);
        m.y = fmaxf(m.y + bb.y, 0.f);
        m.z = fmaxf(m.z + bb.z, 0.f);
        m.w = fmaxf(m.w + bb.w, 0.f);
    }
    ((float4*)out)[(size_t)nid * 4 + c4] = m;
}

// ---------------------------------------------------------------------------
// K5: out = log_softmax( mean2 @ W2 + b2 ).  Thread per node.
// ---------------------------------------------------------------------------
__global__ void out_kernel(const float* __restrict__ W2,
                           const float* __restrict__ b2,
                           const float* __restrict__ mean2,
                           float* __restrict__ out) {
    __shared__ float w2s[HID * OUT_CH];
    __shared__ float b2s[OUT_CH];
    for (int i = threadIdx.x; i < HID * OUT_CH; i += blockDim.x) w2s[i] = W2[i];
    for (int i = threadIdx.x; i < OUT_CH;       i += blockDim.x) b2s[i] = b2[i];
    __syncthreads();

    int n = blockIdx.x * blockDim.x + threadIdx.x;
    if (n >= N_NODES) return;

    const float4* av = (const float4*)(mean2 + (size_t)n * 16);
    float4 m0 = av[0], m1 = av[1], m2 = av[2], m3 = av[3];
    float m[16] = { m0.x, m0.y, m0.z, m0.w, m1.x, m1.y, m1.z, m1.w,
                    m2.x, m2.y, m2.z, m2.w, m3.x, m3.y, m3.z, m3.w };

    float o[OUT_CH];
    #pragma unroll
    for (int j = 0; j < OUT_CH; j++) {
        float s = b2s[j];
        #pragma unroll
        for (int k = 0; k < HID; k++)
            s += m[k] * w2s[k * OUT_CH + j];
        o[j] = s;
    }

    float mx = o[0];
    #pragma unroll
    for (int j = 1; j < OUT_CH; j++) mx = fmaxf(mx, o[j]);
    float sum = 0.0f;
    #pragma unroll
    for (int j = 0; j < OUT_CH; j++) sum += __expf(o[j] - mx);
    float ls = __logf(sum) + mx;

    float* op = out + (size_t)n * OUT_CH;
    #pragma unroll
    for (int j = 0; j < OUT_CH; j++) op[j] = o[j] - ls;
}

// ---------------------------------------------------------------------------
extern "C" void kernel_launch(void* const* d_in, const int* in_sizes, int n_in,
                              void* d_out, int out_size) {
    const float* x  = (const float*)d_in[0];
    const int*   ei = (const int*)  d_in[1];
    const float* W1 = (const float*)d_in[2];
    const float* b1 = (const float*)d_in[3];
    const float* W2 = (const float*)d_in[4];
    const float* b2 = (const float*)d_in[5];
    float* out = (float*)d_out;

    const int* src = ei;
    const int* dst = ei + N_EDGES;

    float *p_h1, *p_r, *p_mean2;
    int *p_deg, *p_excl, *p_blksum, *p_rowptr, *p_cursor, *p_csr;
    cudaGetSymbolAddress((void**)&p_h1,     g_h1);
    cudaGetSymbolAddress((void**)&p_r,      g_r);
    cudaGetSymbolAddress((void**)&p_mean2,  g_mean2);
    cudaGetSymbolAddress((void**)&p_deg,    g_deg);
    cudaGetSymbolAddress((void**)&p_excl,   g_excl);
    cudaGetSymbolAddress((void**)&p_blksum, g_blksum);
    cudaGetSymbolAddress((void**)&p_rowptr, g_rowptr);
    cudaGetSymbolAddress((void**)&p_cursor, g_cursor);
    cudaGetSymbolAddress((void**)&p_csr,    g_csr);

    // Side stream + fork/join events (created on first call, which is the
    // uncaptured correctness run; reused identically during graph capture).
    static cudaStream_t s_csr = nullptr;
    static cudaEvent_t  ev_fork = nullptr, ev_join = nullptr;
    if (s_csr == nullptr) {
        cudaStreamCreateWithFlags(&s_csr, cudaStreamNonBlocking);
        cudaEventCreateWithFlags(&ev_fork, cudaEventDisableTiming);
        cudaEventCreateWithFlags(&ev_join, cudaEventDisableTiming);
    }

    // Fork: CSR chain on side stream, gemm on main stream — independent.
    cudaEventRecord(ev_fork, 0);
    cudaStreamWaitEvent(s_csr, ev_fork, 0);

    cudaMemsetAsync(p_deg, 0, sizeof(int) * N_NODES, s_csr);
    deg_kernel <<<(N_EDGES + 255) / 256, 256, 0, s_csr>>>(dst, p_deg);
    scan1_kernel<<<NB_SCAN, SCAN_BLK, 0, s_csr>>>(p_deg, p_excl, p_blksum);
    scan2_kernel<<<1, 128, 0, s_csr>>>(p_blksum);
    scan3_kernel<<<(N_NODES + 255) / 256, 256, 0, s_csr>>>(p_excl, p_blksum, p_rowptr, p_cursor);
    fill_kernel <<<(N_EDGES + 255) / 256, 256, 0, s_csr>>>(src, dst, p_cursor, p_csr);
    cudaEventRecord(ev_join, s_csr);

    // K1 on main stream, overlapped with CSR build
    gemm1_kernel<<<(N_NODES + M_TILE - 1) / M_TILE, 256>>>(x, W1, p_h1);

    // Join: gather1 needs both h1 and the CSR
    cudaStreamWaitEvent(0, ev_join, 0);

    gather_kernel<true> <<<(N_NODES * 4 + 255) / 256, 256>>>(p_h1, p_rowptr, p_csr, b1, p_r);
    gather_kernel<false><<<(N_NODES * 4 + 255) / 256, 256>>>(p_r, p_rowptr, p_csr, b1, p_mean2);
    out_kernel<<<(N_NODES + 255) / 256, 256>>>(W2, b2, p_mean2, out);
}

// round 11
// speedup vs baseline: 1.6359x; 1.0210x over previous
#include <cuda_runtime.h>
#include <math.h>

#define N_NODES 100000
#define N_EDGES 3200000
#define IN_CH   602
#define HID     16
#define OUT_CH  41

#define M_TILE   256
#define KC       16
#define XS_ROW   (KC + 4)                  // 20 floats: conflict-free LDS.128, 16B-aligned rows
#define NCH      ((IN_CH + KC - 1) / KC)   // 38
#define SCAN_BLK 1024
#define NB_SCAN  ((N_NODES + SCAN_BLK - 1) / SCAN_BLK)   // 98

// Scratch (device globals; no allocation allowed)
__device__ float g_h1   [N_NODES * HID];
__device__ float g_r    [N_NODES * HID];
__device__ float g_mean2[N_NODES * HID];
__device__ int   g_deg  [N_NODES];
__device__ int   g_excl [N_NODES];
__device__ int   g_blksum[128];
__device__ int   g_rowptr[N_NODES + 1];
__device__ int   g_cursor[N_NODES];
__device__ int   g_csr  [N_EDGES];

// ---------------------------------------------------------------------------
// K1: h1[N,16] = x[N,602] @ W1[602,16].
// Staging + double-buffered prefetch identical to the proven round-9 kernel.
// NEW compute mapping: thread = 1 row x 16 cols, so each staged x byte is
// read from smem exactly ONCE (was 8x).  W read as 4 float4 broadcasts per k.
// ---------------------------------------------------------------------------
__global__ __launch_bounds__(256)
void gemm1_kernel(const float* __restrict__ x,
                  const float* __restrict__ W1,
                  float* __restrict__ h1) {
    __shared__ float xs[M_TILE][XS_ROW];
    __shared__ float ws[KC][HID];

    const int tid      = threadIdx.x;
    const int row_base = blockIdx.x * M_TILE;
    const int rl = tid;              // compute: local row (1 row per thread)

    const int pr = tid >> 3;         // prefetch row lane 0..31
    const int pk = (tid & 7) * 2;    // prefetch k-pair 0,2,...,14
    const int wk = tid >> 4;         // W: k row 0..15
    const int wc = tid & 15;         // W: col

    float2 px[8];
    float  pw;

    float acc[16];
    #pragma unroll
    for (int j = 0; j < 16; j++) acc[j] = 0.f;

    // ---- prefetch chunk 0 ----
    {
        const int kc = 0;
        #pragma unroll
        for (int i = 0; i < 8; i++) {
            int r = i * 32 + pr;
            int grow = row_base + r;
            int cr = (grow < N_NODES) ? grow : 0;
            int gk = kc + pk;
            float2 v = make_float2(0.f, 0.f);
            if (gk + 1 < IN_CH) v = *(const float2*)(x + (size_t)cr * IN_CH + gk);
            px[i] = v;
        }
        pw = (kc + wk < IN_CH) ? W1[(size_t)(kc + wk) * HID + wc] : 0.f;
    }

    #pragma unroll 1
    for (int c = 0; c < NCH; c++) {
        // store staged chunk (STS.64, 8B-aligned, conflict-free)
        #pragma unroll
        for (int i = 0; i < 8; i++) {
            *(float2*)&xs[i * 32 + pr][pk] = px[i];
        }
        ws[wk][wc] = pw;
        __syncthreads();

        // prefetch chunk c+1 (LDGs overlap the compute below)
        if (c + 1 < NCH) {
            const int kc = (c + 1) * KC;
            #pragma unroll
            for (int i = 0; i < 8; i++) {
                int r = i * 32 + pr;
                int grow = row_base + r;
                int cr = (grow < N_NODES) ? grow : 0;
                int gk = kc + pk;
                float2 v = make_float2(0.f, 0.f);
                if (gk + 1 < IN_CH) v = *(const float2*)(x + (size_t)cr * IN_CH + gk);
                px[i] = v;
            }
            pw = (kc + wk < IN_CH) ? W1[(size_t)(kc + wk) * HID + wc] : 0.f;
        }

        // compute current chunk: one LDS.128 of x per k4, W as broadcasts
        #pragma unroll
        for (int k0 = 0; k0 < KC; k0 += 4) {
            float4 xv = *(const float4*)&xs[rl][k0];
            #pragma unroll
            for (int kk = 0; kk < 4; kk++) {
                float xk = (kk == 0) ? xv.x : (kk == 1) ? xv.y
                         : (kk == 2) ? xv.z : xv.w;
                float4 w0 = *(const float4*)&ws[k0 + kk][0];
                float4 w1 = *(const float4*)&ws[k0 + kk][4];
                float4 w2 = *(const float4*)&ws[k0 + kk][8];
                float4 w3 = *(const float4*)&ws[k0 + kk][12];
                acc[0]  += xk * w0.x;  acc[1]  += xk * w0.y;
                acc[2]  += xk * w0.z;  acc[3]  += xk * w0.w;
                acc[4]  += xk * w1.x;  acc[5]  += xk * w1.y;
                acc[6]  += xk * w1.z;  acc[7]  += xk * w1.w;
                acc[8]  += xk * w2.x;  acc[9]  += xk * w2.y;
                acc[10] += xk * w2.z;  acc[11] += xk * w2.w;
                acc[12] += xk * w3.x;  acc[13] += xk * w3.y;
                acc[14] += xk * w3.z;  acc[15] += xk * w3.w;
            }
        }
        __syncthreads();
    }

    int row = row_base + rl;
    if (row < N_NODES) {
        float* op = h1 + (size_t)row * 16;
        #pragma unroll
        for (int q = 0; q < 4; q++) {
            float4 v = make_float4(acc[q*4+0], acc[q*4+1], acc[q*4+2], acc[q*4+3]);
            *(float4*)(op + q * 4) = v;
        }
    }
}

// ---------------------------------------------------------------------------
// CSR construction  (proven path)
// ---------------------------------------------------------------------------
__global__ void deg_kernel(const int* __restrict__ dst, int* __restrict__ deg) {
    int e = blockIdx.x * blockDim.x + threadIdx.x;
    if (e < N_EDGES) atomicAdd(&deg[dst[e]], 1);
}

__global__ __launch_bounds__(SCAN_BLK)
void scan1_kernel(const int* __restrict__ deg,
                  int* __restrict__ excl,
                  int* __restrict__ blksum) {
    __shared__ int wsum[32];
    int tid = threadIdx.x, lane = tid & 31, wid = tid >> 5;
    int i = blockIdx.x * SCAN_BLK + tid;
    int v = (i < N_NODES) ? deg[i] : 0;
    int x = v;
    #pragma unroll
    for (int d = 1; d < 32; d <<= 1) {
        int t = __shfl_up_sync(0xffffffffu, x, d);
        if (lane >= d) x += t;
    }
    if (lane == 31) wsum[wid] = x;
    __syncthreads();
    if (wid == 0) {
        int s = wsum[lane];
        #pragma unroll
        for (int d = 1; d < 32; d <<= 1) {
            int t = __shfl_up_sync(0xffffffffu, s, d);
            if (lane >= d) s += t;
        }
        wsum[lane] = s;
    }
    __syncthreads();
    int woff = (wid == 0) ? 0 : wsum[wid - 1];
    if (i < N_NODES) excl[i] = woff + x - v;
    if (tid == SCAN_BLK - 1) blksum[blockIdx.x] = wsum[31];
}

__global__ __launch_bounds__(128)
void scan2_kernel(int* __restrict__ blksum) {
    __shared__ int ws[4];
    int tid = threadIdx.x, lane = tid & 31, wid = tid >> 5;
    int v = (tid < NB_SCAN) ? blksum[tid] : 0;
    int x = v;
    #pragma unroll
    for (int d = 1; d < 32; d <<= 1) {
        int t = __shfl_up_sync(0xffffffffu, x, d);
        if (lane >= d) x += t;
    }
    if (lane == 31) ws[wid] = x;
    __syncthreads();
    int woff = 0;
    #pragma unroll
    for (int w = 0; w < 4; w++) if (w < wid) woff += ws[w];
    if (tid < NB_SCAN) blksum[tid] = woff + x - v;
}

__global__ void scan3_kernel(const int* __restrict__ excl,
                             const int* __restrict__ blksum,
                             int* __restrict__ rowptr,
                             int* __restrict__ cursor) {
    int i = blockIdx.x * blockDim.x + threadIdx.x;
    if (i >= N_NODES) return;
    int v = excl[i] + blksum[i / SCAN_BLK];
    rowptr[i] = v;
    cursor[i] = v;
    if (i == 0) rowptr[N_NODES] = N_EDGES;
}

__global__ void fill_kernel(const int* __restrict__ src,
                            const int* __restrict__ dst,
                            int* __restrict__ cursor,
                            int* __restrict__ csr_src) {
    int e = blockIdx.x * blockDim.x + threadIdx.x;
    if (e >= N_EDGES) return;
    int slot = atomicAdd(&cursor[dst[e]], 1);
    csr_src[slot] = src[e];
}

// ---------------------------------------------------------------------------
// Gather layer: 4 threads per node (lane = 4-channel group, float4 loads).
// ---------------------------------------------------------------------------
template <bool RELU>
__global__ void gather_kernel(const float* __restrict__ h,
                              const int* __restrict__ rowptr,
                              const int* __restrict__ csr_src,
                              const float* __restrict__ bias,
                              float* __restrict__ out) {
    int t = blockIdx.x * blockDim.x + threadIdx.x;
    int nid = t >> 2;
    int c4  = t & 3;
    if (nid >= N_NODES) return;
    int beg = rowptr[nid];
    int end = rowptr[nid + 1];
    const float4* hv = (const float4*)h;
    float4 s = make_float4(0.f, 0.f, 0.f, 0.f);
    int j = beg;
    for (; j + 4 <= end; j += 4) {
        int s0 = csr_src[j], s1 = csr_src[j + 1],
            s2 = csr_src[j + 2], s3 = csr_src[j + 3];
        float4 v0 = hv[(size_t)s0 * 4 + c4];
        float4 v1 = hv[(size_t)s1 * 4 + c4];
        float4 v2 = hv[(size_t)s2 * 4 + c4];
        float4 v3 = hv[(size_t)s3 * 4 + c4];
        s.x += (v0.x + v1.x) + (v2.x + v3.x);
        s.y += (v0.y + v1.y) + (v2.y + v3.y);
        s.z += (v0.z + v1.z) + (v2.z + v3.z);
        s.w += (v0.w + v1.w) + (v2.w + v3.w);
    }
    for (; j < end; j++) {
        float4 v = hv[(size_t)csr_src[j] * 4 + c4];
        s.x += v.x; s.y += v.y; s.z += v.z; s.w += v.w;
    }
    float inv = 1.f / fmaxf((float)(end - beg), 1.f);
    float4 m;
    m.x = s.x * inv; m.y = s.y * inv; m.z = s.z * inv; m.w = s.w * inv;
    if (RELU) {
        float4 bb = __ldg(((const float4*)bias) + c4);
        m.x = fmaxf(m.x + bb.x, 0.f);
        m.y = fmaxf(m.y + bb.y, 0.f);
        m.z = fmaxf(m.z + bb.z, 0.f);
        m.w = fmaxf(m.w + bb.w, 0.f);
    }
    ((float4*)out)[(size_t)nid * 4 + c4] = m;
}

// ---------------------------------------------------------------------------
// K5: out = log_softmax( mean2 @ W2 + b2 ).  Thread per node.
// ---------------------------------------------------------------------------
__global__ void out_kernel(const float* __restrict__ W2,
                           const float* __restrict__ b2,
                           const float* __restrict__ mean2,
                           float* __restrict__ out) {
    __shared__ float w2s[HID * OUT_CH];
    __shared__ float b2s[OUT_CH];
    for (int i = threadIdx.x; i < HID * OUT_CH; i += blockDim.x) w2s[i] = W2[i];
    for (int i = threadIdx.x; i < OUT_CH;       i += blockDim.x) b2s[i] = b2[i];
    __syncthreads();

    int n = blockIdx.x * blockDim.x + threadIdx.x;
    if (n >= N_NODES) return;

    const float4* av = (const float4*)(mean2 + (size_t)n * 16);
    float4 m0 = av[0], m1 = av[1], m2 = av[2], m3 = av[3];
    float m[16] = { m0.x, m0.y, m0.z, m0.w, m1.x, m1.y, m1.z, m1.w,
                    m2.x, m2.y, m2.z, m2.w, m3.x, m3.y, m3.z, m3.w };

    float o[OUT_CH];
    #pragma unroll
    for (int j = 0; j < OUT_CH; j++) {
        float s = b2s[j];
        #pragma unroll
        for (int k = 0; k < HID; k++)
            s += m[k] * w2s[k * OUT_CH + j];
        o[j] = s;
    }

    float mx = o[0];
    #pragma unroll
    for (int j = 1; j < OUT_CH; j++) mx = fmaxf(mx, o[j]);
    float sum = 0.0f;
    #pragma unroll
    for (int j = 0; j < OUT_CH; j++) sum += __expf(o[j] - mx);
    float ls = __logf(sum) + mx;

    float* op = out + (size_t)n * OUT_CH;
    #pragma unroll
    for (int j = 0; j < OUT_CH; j++) op[j] = o[j] - ls;
}

// ---------------------------------------------------------------------------
extern "C" void kernel_launch(void* const* d_in, const int* in_sizes, int n_in,
                              void* d_out, int out_size) {
    const float* x  = (const float*)d_in[0];
    const int*   ei = (const int*)  d_in[1];
    const float* W1 = (const float*)d_in[2];
    const float* b1 = (const float*)d_in[3];
    const float* W2 = (const float*)d_in[4];
    const float* b2 = (const float*)d_in[5];
    float* out = (float*)d_out;

    const int* src = ei;
    const int* dst = ei + N_EDGES;

    float *p_h1, *p_r, *p_mean2;
    int *p_deg, *p_excl, *p_blksum, *p_rowptr, *p_cursor, *p_csr;
    cudaGetSymbolAddress((void**)&p_h1,     g_h1);
    cudaGetSymbolAddress((void**)&p_r,      g_r);
    cudaGetSymbolAddress((void**)&p_mean2,  g_mean2);
    cudaGetSymbolAddress((void**)&p_deg,    g_deg);
    cudaGetSymbolAddress((void**)&p_excl,   g_excl);
    cudaGetSymbolAddress((void**)&p_blksum, g_blksum);
    cudaGetSymbolAddress((void**)&p_rowptr, g_rowptr);
    cudaGetSymbolAddress((void**)&p_cursor, g_cursor);
    cudaGetSymbolAddress((void**)&p_csr,    g_csr);

    // Side stream + fork/join events (created on first call, which is the
    // uncaptured correctness run; reused identically during graph capture).
    static cudaStream_t s_csr = nullptr;
    static cudaEvent_t  ev_fork = nullptr, ev_join = nullptr;
    if (s_csr == nullptr) {
        cudaStreamCreateWithFlags(&s_csr, cudaStreamNonBlocking);
        cudaEventCreateWithFlags(&ev_fork, cudaEventDisableTiming);
        cudaEventCreateWithFlags(&ev_join, cudaEventDisableTiming);
    }

    // Fork: CSR chain on side stream, gemm on main stream — independent.
    cudaEventRecord(ev_fork, 0);
    cudaStreamWaitEvent(s_csr, ev_fork, 0);

    cudaMemsetAsync(p_deg, 0, sizeof(int) * N_NODES, s_csr);
    deg_kernel <<<(N_EDGES + 255) / 256, 256, 0, s_csr>>>(dst, p_deg);
    scan1_kernel<<<NB_SCAN, SCAN_BLK, 0, s_csr>>>(p_deg, p_excl, p_blksum);
    scan2_kernel<<<1, 128, 0, s_csr>>>(p_blksum);
    scan3_kernel<<<(N_NODES + 255) / 256, 256, 0, s_csr>>>(p_excl, p_blksum, p_rowptr, p_cursor);
    fill_kernel <<<(N_EDGES + 255) / 256, 256, 0, s_csr>>>(src, dst, p_cursor, p_csr);
    cudaEventRecord(ev_join, s_csr);

    // K1 on main stream, overlapped with CSR build
    gemm1_kernel<<<(N_NODES + M_TILE - 1) / M_TILE, 256>>>(x, W1, p_h1);

    // Join: gather1 needs both h1 and the CSR
    cudaStreamWaitEvent(0, ev_join, 0);

    gather_kernel<true> <<<(N_NODES * 4 + 255) / 256, 256>>>(p_h1, p_rowptr, p_csr, b1, p_r);
    gather_kernel<false><<<(N_NODES * 4 + 255) / 256, 256>>>(p_r, p_rowptr, p_csr, b1, p_mean2);
    out_kernel<<<(N_NODES + 255) / 256, 256>>>(W2, b2, p_mean2, out);
}

// round 13
// speedup vs baseline: 1.7987x; 1.0996x over previous
#include <cuda_runtime.h>
#include <math.h>

#define N_NODES 100000
#define N_EDGES 3200000
#define IN_CH   602
#define HID     16
#define OUT_CH  41

#define M_TILE   256
#define KC       16
#define XS_ROW   (KC + 4)                  // 20 floats: conflict-free LDS.128, 16B-aligned rows
#define NCH      ((IN_CH + KC - 1) / KC)   // 38
#define SCAN_BLK 1024
#define NB_SCAN  ((N_NODES + SCAN_BLK - 1) / SCAN_BLK)   // 98

// Scratch (device globals; no allocation allowed)
__device__ float g_h1   [N_NODES * HID];
__device__ float g_r    [N_NODES * HID];
__device__ int   g_deg  [N_NODES];
__device__ int   g_excl [N_NODES];
__device__ int   g_blksum[128];
__device__ int   g_rowptr[N_NODES + 1];
__device__ int   g_cursor[N_NODES];
__device__ int   g_csr  [N_EDGES];

// ---------------------------------------------------------------------------
// K1: h1[N,16] = x[N,602] @ W1[602,16].  (proven round-11 version)
// ---------------------------------------------------------------------------
__global__ __launch_bounds__(256)
void gemm1_kernel(const float* __restrict__ x,
                  const float* __restrict__ W1,
                  float* __restrict__ h1) {
    __shared__ float xs[M_TILE][XS_ROW];
    __shared__ float ws[KC][HID];

    const int tid      = threadIdx.x;
    const int row_base = blockIdx.x * M_TILE;
    const int rl = tid;              // compute: local row (1 row per thread)

    const int pr = tid >> 3;         // prefetch row lane 0..31
    const int pk = (tid & 7) * 2;    // prefetch k-pair 0,2,...,14
    const int wk = tid >> 4;         // W: k row 0..15
    const int wc = tid & 15;         // W: col

    float2 px[8];
    float  pw;

    float acc[16];
    #pragma unroll
    for (int j = 0; j < 16; j++) acc[j] = 0.f;

    // ---- prefetch chunk 0 ----
    {
        const int kc = 0;
        #pragma unroll
        for (int i = 0; i < 8; i++) {
            int r = i * 32 + pr;
            int grow = row_base + r;
            int cr = (grow < N_NODES) ? grow : 0;
            int gk = kc + pk;
            float2 v = make_float2(0.f, 0.f);
            if (gk + 1 < IN_CH) v = *(const float2*)(x + (size_t)cr * IN_CH + gk);
            px[i] = v;
        }
        pw = (kc + wk < IN_CH) ? W1[(size_t)(kc + wk) * HID + wc] : 0.f;
    }

    #pragma unroll 1
    for (int c = 0; c < NCH; c++) {
        #pragma unroll
        for (int i = 0; i < 8; i++) {
            *(float2*)&xs[i * 32 + pr][pk] = px[i];
        }
        ws[wk][wc] = pw;
        __syncthreads();

        if (c + 1 < NCH) {
            const int kc = (c + 1) * KC;
            #pragma unroll
            for (int i = 0; i < 8; i++) {
                int r = i * 32 + pr;
                int grow = row_base + r;
                int cr = (grow < N_NODES) ? grow : 0;
                int gk = kc + pk;
                float2 v = make_float2(0.f, 0.f);
                if (gk + 1 < IN_CH) v = *(const float2*)(x + (size_t)cr * IN_CH + gk);
                px[i] = v;
            }
            pw = (kc + wk < IN_CH) ? W1[(size_t)(kc + wk) * HID + wc] : 0.f;
        }

        #pragma unroll
        for (int k0 = 0; k0 < KC; k0 += 4) {
            float4 xv = *(const float4*)&xs[rl][k0];
            #pragma unroll
            for (int kk = 0; kk < 4; kk++) {
                float xk = (kk == 0) ? xv.x : (kk == 1) ? xv.y
                         : (kk == 2) ? xv.z : xv.w;
                float4 w0 = *(const float4*)&ws[k0 + kk][0];
                float4 w1 = *(const float4*)&ws[k0 + kk][4];
                float4 w2 = *(const float4*)&ws[k0 + kk][8];
                float4 w3 = *(const float4*)&ws[k0 + kk][12];
                acc[0]  += xk * w0.x;  acc[1]  += xk * w0.y;
                acc[2]  += xk * w0.z;  acc[3]  += xk * w0.w;
                acc[4]  += xk * w1.x;  acc[5]  += xk * w1.y;
                acc[6]  += xk * w1.z;  acc[7]  += xk * w1.w;
                acc[8]  += xk * w2.x;  acc[9]  += xk * w2.y;
                acc[10] += xk * w2.z;  acc[11] += xk * w2.w;
                acc[12] += xk * w3.x;  acc[13] += xk * w3.y;
                acc[14] += xk * w3.z;  acc[15] += xk * w3.w;
            }
        }
        __syncthreads();
    }

    int row = row_base + rl;
    if (row < N_NODES) {
        float* op = h1 + (size_t)row * 16;
        #pragma unroll
        for (int q = 0; q < 4; q++) {
            float4 v = make_float4(acc[q*4+0], acc[q*4+1], acc[q*4+2], acc[q*4+3]);
            *(float4*)(op + q * 4) = v;
        }
    }
}

// ---------------------------------------------------------------------------
// CSR construction  (proven path)
// ---------------------------------------------------------------------------
__global__ void deg_kernel(const int* __restrict__ dst, int* __restrict__ deg) {
    int e = blockIdx.x * blockDim.x + threadIdx.x;
    if (e < N_EDGES) atomicAdd(&deg[dst[e]], 1);
}

__global__ __launch_bounds__(SCAN_BLK)
void scan1_kernel(const int* __restrict__ deg,
                  int* __restrict__ excl,
                  int* __restrict__ blksum) {
    __shared__ int wsum[32];
    int tid = threadIdx.x, lane = tid & 31, wid = tid >> 5;
    int i = blockIdx.x * SCAN_BLK + tid;
    int v = (i < N_NODES) ? deg[i] : 0;
    int x = v;
    #pragma unroll
    for (int d = 1; d < 32; d <<= 1) {
        int t = __shfl_up_sync(0xffffffffu, x, d);
        if (lane >= d) x += t;
    }
    if (lane == 31) wsum[wid] = x;
    __syncthreads();
    if (wid == 0) {
        int s = wsum[lane];
        #pragma unroll
        for (int d = 1; d < 32; d <<= 1) {
            int t = __shfl_up_sync(0xffffffffu, s, d);
            if (lane >= d) s += t;
        }
        wsum[lane] = s;
    }
    __syncthreads();
    int woff = (wid == 0) ? 0 : wsum[wid - 1];
    if (i < N_NODES) excl[i] = woff + x - v;
    if (tid == SCAN_BLK - 1) blksum[blockIdx.x] = wsum[31];
}

__global__ __launch_bounds__(128)
void scan2_kernel(int* __restrict__ blksum) {
    __shared__ int ws[4];
    int tid = threadIdx.x, lane = tid & 31, wid = tid >> 5;
    int v = (tid < NB_SCAN) ? blksum[tid] : 0;
    int x = v;
    #pragma unroll
    for (int d = 1; d < 32; d <<= 1) {
        int t = __shfl_up_sync(0xffffffffu, x, d);
        if (lane >= d) x += t;
    }
    if (lane == 31) ws[wid] = x;
    __syncthreads();
    int woff = 0;
    #pragma unroll
    for (int w = 0; w < 4; w++) if (w < wid) woff += ws[w];
    if (tid < NB_SCAN) blksum[tid] = woff + x - v;
}

__global__ void scan3_kernel(const int* __restrict__ excl,
                             const int* __restrict__ blksum,
                             int* __restrict__ rowptr,
                             int* __restrict__ cursor) {
    int i = blockIdx.x * blockDim.x + threadIdx.x;
    if (i >= N_NODES) return;
    int v = excl[i] + blksum[i / SCAN_BLK];
    rowptr[i] = v;
    cursor[i] = v;
    if (i == 0) rowptr[N_NODES] = N_EDGES;
}

__global__ void fill_kernel(const int* __restrict__ src,
                            const int* __restrict__ dst,
                            int* __restrict__ cursor,
                            int* __restrict__ csr_src) {
    int e = blockIdx.x * blockDim.x + threadIdx.x;
    if (e >= N_EDGES) return;
    int slot = atomicAdd(&cursor[dst[e]], 1);
    csr_src[slot] = src[e];
}

// ---------------------------------------------------------------------------
// Gather layer 1: 4 threads per node, float4 loads, csr indices deduped via
// GROUP-MASKED width-4 shuffles (mask = the 4-lane group only; the group
// shares beg/end so its lanes are always convergent at the shuffle).
// ---------------------------------------------------------------------------
__global__ void gather1_kernel(const float* __restrict__ h,
                               const int* __restrict__ rowptr,
                               const int* __restrict__ csr_src,
                               const float* __restrict__ bias,
                               float* __restrict__ out) {
    int t = blockIdx.x * blockDim.x + threadIdx.x;
    int nid = t >> 2;
    int c4  = t & 3;
    unsigned gmask = 0xFu << ((threadIdx.x & 31) & ~3);   // this 4-lane group
    if (nid >= N_NODES) return;
    int beg = rowptr[nid];
    int end = rowptr[nid + 1];
    const float4* hv = (const float4*)h;
    float4 s = make_float4(0.f, 0.f, 0.f, 0.f);
    int j = beg;
    for (; j + 4 <= end; j += 4) {
        int myi = csr_src[j + c4];
        int s0 = __shfl_sync(gmask, myi, 0, 4);
        int s1 = __shfl_sync(gmask, myi, 1, 4);
        int s2 = __shfl_sync(gmask, myi, 2, 4);
        int s3 = __shfl_sync(gmask, myi, 3, 4);
        float4 v0 = hv[(size_t)s0 * 4 + c4];
        float4 v1 = hv[(size_t)s1 * 4 + c4];
        float4 v2 = hv[(size_t)s2 * 4 + c4];
        float4 v3 = hv[(size_t)s3 * 4 + c4];
        s.x += (v0.x + v1.x) + (v2.x + v3.x);
        s.y += (v0.y + v1.y) + (v2.y + v3.y);
        s.z += (v0.z + v1.z) + (v2.z + v3.z);
        s.w += (v0.w + v1.w) + (v2.w + v3.w);
    }
    for (; j < end; j++) {
        float4 v = hv[(size_t)csr_src[j] * 4 + c4];
        s.x += v.x; s.y += v.y; s.z += v.z; s.w += v.w;
    }
    float inv = 1.f / fmaxf((float)(end - beg), 1.f);
    float4 m;
    m.x = s.x * inv; m.y = s.y * inv; m.z = s.z * inv; m.w = s.w * inv;
    float4 bb = __ldg(((const float4*)bias) + c4);
    m.x = fmaxf(m.x + bb.x, 0.f);
    m.y = fmaxf(m.y + bb.y, 0.f);
    m.z = fmaxf(m.z + bb.z, 0.f);
    m.w = fmaxf(m.w + bb.w, 0.f);
    ((float4*)out)[(size_t)nid * 4 + c4] = m;
}

// ---------------------------------------------------------------------------
// Fused gather2 + W2 matvec + log_softmax.  4 threads per node.
// mean2 never touches gmem.  All shuffles use the group-local mask.
// ---------------------------------------------------------------------------
__global__ void gather2_out_kernel(const float* __restrict__ h,
                                   const int* __restrict__ rowptr,
                                   const int* __restrict__ csr_src,
                                   const float* __restrict__ W2,
                                   const float* __restrict__ b2,
                                   float* __restrict__ out) {
    __shared__ float w2s[HID * OUT_CH];
    __shared__ float b2s[OUT_CH];
    for (int i = threadIdx.x; i < HID * OUT_CH; i += blockDim.x) w2s[i] = W2[i];
    for (int i = threadIdx.x; i < OUT_CH;       i += blockDim.x) b2s[i] = b2[i];
    __syncthreads();

    int t = blockIdx.x * blockDim.x + threadIdx.x;
    int nid = t >> 2;
    int c4  = t & 3;
    unsigned gmask = 0xFu << ((threadIdx.x & 31) & ~3);   // this 4-lane group
    if (nid >= N_NODES) return;
    int beg = rowptr[nid];
    int end = rowptr[nid + 1];
    const float4* hv = (const float4*)h;
    float4 s = make_float4(0.f, 0.f, 0.f, 0.f);
    int j = beg;
    for (; j + 4 <= end; j += 4) {
        int myi = csr_src[j + c4];
        int s0 = __shfl_sync(gmask, myi, 0, 4);
        int s1 = __shfl_sync(gmask, myi, 1, 4);
        int s2 = __shfl_sync(gmask, myi, 2, 4);
        int s3 = __shfl_sync(gmask, myi, 3, 4);
        float4 v0 = hv[(size_t)s0 * 4 + c4];
        float4 v1 = hv[(size_t)s1 * 4 + c4];
        float4 v2 = hv[(size_t)s2 * 4 + c4];
        float4 v3 = hv[(size_t)s3 * 4 + c4];
        s.x += (v0.x + v1.x) + (v2.x + v3.x);
        s.y += (v0.y + v1.y) + (v2.y + v3.y);
        s.z += (v0.z + v1.z) + (v2.z + v3.z);
        s.w += (v0.w + v1.w) + (v2.w + v3.w);
    }
    for (; j < end; j++) {
        float4 v = hv[(size_t)csr_src[j] * 4 + c4];
        s.x += v.x; s.y += v.y; s.z += v.z; s.w += v.w;
    }
    float inv = 1.f / fmaxf((float)(end - beg), 1.f);
    float4 m;
    m.x = s.x * inv; m.y = s.y * inv; m.z = s.z * inv; m.w = s.w * inv;

    // share the 16 mean channels across the 4-lane group
    float ma[16];
    #pragma unroll
    for (int sl = 0; sl < 4; sl++) {
        ma[sl * 4 + 0] = __shfl_sync(gmask, m.x, sl, 4);
        ma[sl * 4 + 1] = __shfl_sync(gmask, m.y, sl, 4);
        ma[sl * 4 + 2] = __shfl_sync(gmask, m.z, sl, 4);
        ma[sl * 4 + 3] = __shfl_sync(gmask, m.w, sl, 4);
    }

    // each lane computes logits j = c4 + 4*i  (11 slots; last may be unused)
    float o[11];
    float lmax = -1e30f;
    int cnt = 0;
    for (int jj = c4; jj < OUT_CH; jj += 4, cnt++) {
        float v = b2s[jj];
        #pragma unroll
        for (int k = 0; k < HID; k++)
            v += ma[k] * w2s[k * OUT_CH + jj];
        o[cnt] = v;
        lmax = fmaxf(lmax, v);
    }
    // group reductions (xor 1, 2 stay inside the 4-lane group)
    lmax = fmaxf(lmax, __shfl_xor_sync(gmask, lmax, 1));
    lmax = fmaxf(lmax, __shfl_xor_sync(gmask, lmax, 2));
    float lsum = 0.f;
    for (int i = 0; i < cnt; i++) lsum += __expf(o[i] - lmax);
    lsum += __shfl_xor_sync(gmask, lsum, 1);
    lsum += __shfl_xor_sync(gmask, lsum, 2);
    float ls = __logf(lsum) + lmax;

    float* op = out + (size_t)nid * OUT_CH;
    int i = 0;
    for (int jj = c4; jj < OUT_CH; jj += 4, i++) op[jj] = o[i] - ls;
}

// ---------------------------------------------------------------------------
extern "C" void kernel_launch(void* const* d_in, const int* in_sizes, int n_in,
                              void* d_out, int out_size) {
    const float* x  = (const float*)d_in[0];
    const int*   ei = (const int*)  d_in[1];
    const float* W1 = (const float*)d_in[2];
    const float* b1 = (const float*)d_in[3];
    const float* W2 = (const float*)d_in[4];
    const float* b2 = (const float*)d_in[5];
    float* out = (float*)d_out;

    const int* src = ei;
    const int* dst = ei + N_EDGES;

    float *p_h1, *p_r;
    int *p_deg, *p_excl, *p_blksum, *p_rowptr, *p_cursor, *p_csr;
    cudaGetSymbolAddress((void**)&p_h1,     g_h1);
    cudaGetSymbolAddress((void**)&p_r,      g_r);
    cudaGetSymbolAddress((void**)&p_deg,    g_deg);
    cudaGetSymbolAddress((void**)&p_excl,   g_excl);
    cudaGetSymbolAddress((void**)&p_blksum, g_blksum);
    cudaGetSymbolAddress((void**)&p_rowptr, g_rowptr);
    cudaGetSymbolAddress((void**)&p_cursor, g_cursor);
    cudaGetSymbolAddress((void**)&p_csr,    g_csr);

    // Side stream + fork/join events (created on first call, which is the
    // uncaptured correctness run; reused identically during graph capture).
    static cudaStream_t s_csr = nullptr;
    static cudaEvent_t  ev_fork = nullptr, ev_join = nullptr;
    if (s_csr == nullptr) {
        cudaStreamCreateWithFlags(&s_csr, cudaStreamNonBlocking);
        cudaEventCreateWithFlags(&ev_fork, cudaEventDisableTiming);
        cudaEventCreateWithFlags(&ev_join, cudaEventDisableTiming);
    }

    // Fork: CSR chain on side stream, gemm on main stream — independent.
    cudaEventRecord(ev_fork, 0);
    cudaStreamWaitEvent(s_csr, ev_fork, 0);

    cudaMemsetAsync(p_deg, 0, sizeof(int) * N_NODES, s_csr);
    deg_kernel <<<(N_EDGES + 255) / 256, 256, 0, s_csr>>>(dst, p_deg);
    scan1_kernel<<<NB_SCAN, SCAN_BLK, 0, s_csr>>>(p_deg, p_excl, p_blksum);
    scan2_kernel<<<1, 128, 0, s_csr>>>(p_blksum);
    scan3_kernel<<<(N_NODES + 255) / 256, 256, 0, s_csr>>>(p_excl, p_blksum, p_rowptr, p_cursor);
    fill_kernel <<<(N_EDGES + 255) / 256, 256, 0, s_csr>>>(src, dst, p_cursor, p_csr);
    cudaEventRecord(ev_join, s_csr);

    // K1 on main stream, overlapped with CSR build
    gemm1_kernel<<<(N_NODES + M_TILE - 1) / M_TILE, 256>>>(x, W1, p_h1);

    // Join: gather1 needs both h1 and the CSR
    cudaStreamWaitEvent(0, ev_join, 0);

    gather1_kernel<<<(N_NODES * 4 + 255) / 256, 256>>>(p_h1, p_rowptr, p_csr, b1, p_r);
    gather2_out_kernel<<<(N_NODES * 4 + 255) / 256, 256>>>(p_r, p_rowptr, p_csr, W2, b2, out);
}

// round 14
// speedup vs baseline: 1.8151x; 1.0091x over previous
#include <cuda_runtime.h>
#include <math.h>
#include <stdint.h>

#define N_NODES 100000
#define N_EDGES 3200000
#define IN_CH   602
#define HID     16
#define OUT_CH  41

#define M_TILE   256
#define KC       16
#define XS_ROW   (KC + 4)                  // 20 floats: conflict-free LDS.128, 16B-aligned rows
#define NCH      ((IN_CH + KC - 1) / KC)   // 38
#define SCAN_BLK 1024
#define NB_SCAN  ((N_NODES + SCAN_BLK - 1) / SCAN_BLK)   // 98

// packed f32x2 FMA: acc = a*b + acc  (per-lane IEEE fp32)
#define FMA2(acc, a, b) \
    asm volatile("fma.rn.f32x2 %0, %1, %2, %0;" : "+l"(acc) : "l"(a), "l"(b))

// Scratch (device globals; no allocation allowed)
__device__ float g_h1   [N_NODES * HID];
__device__ float g_r    [N_NODES * HID];
__device__ int   g_deg  [N_NODES];
__device__ int   g_excl [N_NODES];
__device__ int   g_blksum[128];
__device__ int   g_rowptr[N_NODES + 1];
__device__ int   g_cursor[N_NODES];
__device__ int   g_csr  [N_EDGES];

// ---------------------------------------------------------------------------
// K1: h1[N,16] = x[N,602] @ W1[602,16].
// Round-11 staging/pipeline + NEW packed f32x2 inner loop:
// 8 fma.rn.f32x2 per k (was 16 FFMA), W pairs straight from LDS.128.
// ---------------------------------------------------------------------------
__global__ __launch_bounds__(256)
void gemm1_kernel(const float* __restrict__ x,
                  const float* __restrict__ W1,
                  float* __restrict__ h1) {
    __shared__ float xs[M_TILE][XS_ROW];
    __shared__ __align__(16) float ws[KC][HID];

    const int tid      = threadIdx.x;
    const int row_base = blockIdx.x * M_TILE;
    const int rl = tid;              // compute: local row (1 row per thread)

    const int pr = tid >> 3;         // prefetch row lane 0..31
    const int pk = (tid & 7) * 2;    // prefetch k-pair 0,2,...,14
    const int wk = tid >> 4;         // W: k row 0..15
    const int wc = tid & 15;         // W: col

    float2 px[8];
    float  pw;

    uint64_t accp[8];                // 8 packed f32x2 accumulators = 16 cols
    #pragma unroll
    for (int j = 0; j < 8; j++) accp[j] = 0ull;

    // ---- prefetch chunk 0 ----
    {
        const int kc = 0;
        #pragma unroll
        for (int i = 0; i < 8; i++) {
            int r = i * 32 + pr;
            int grow = row_base + r;
            int cr = (grow < N_NODES) ? grow : 0;
            int gk = kc + pk;
            float2 v = make_float2(0.f, 0.f);
            if (gk + 1 < IN_CH) v = *(const float2*)(x + (size_t)cr * IN_CH + gk);
            px[i] = v;
        }
        pw = (kc + wk < IN_CH) ? W1[(size_t)(kc + wk) * HID + wc] : 0.f;
    }

    #pragma unroll 1
    for (int c = 0; c < NCH; c++) {
        #pragma unroll
        for (int i = 0; i < 8; i++) {
            *(float2*)&xs[i * 32 + pr][pk] = px[i];
        }
        ws[wk][wc] = pw;
        __syncthreads();

        if (c + 1 < NCH) {
            const int kc = (c + 1) * KC;
            #pragma unroll
            for (int i = 0; i < 8; i++) {
                int r = i * 32 + pr;
                int grow = row_base + r;
                int cr = (grow < N_NODES) ? grow : 0;
                int gk = kc + pk;
                float2 v = make_float2(0.f, 0.f);
                if (gk + 1 < IN_CH) v = *(const float2*)(x + (size_t)cr * IN_CH + gk);
                px[i] = v;
            }
            pw = (kc + wk < IN_CH) ? W1[(size_t)(kc + wk) * HID + wc] : 0.f;
        }

        #pragma unroll
        for (int k0 = 0; k0 < KC; k0 += 4) {
            float4 xv = *(const float4*)&xs[rl][k0];
            #pragma unroll
            for (int kk = 0; kk < 4; kk++) {
                float xk = (kk == 0) ? xv.x : (kk == 1) ? xv.y
                         : (kk == 2) ? xv.z : xv.w;
                uint64_t xk2;
                asm("mov.b64 %0, {%1, %1};" : "=l"(xk2) : "f"(xk));
                ulonglong2 wA = *(const ulonglong2*)&ws[k0 + kk][0];
                ulonglong2 wB = *(const ulonglong2*)&ws[k0 + kk][4];
                ulonglong2 wC = *(const ulonglong2*)&ws[k0 + kk][8];
                ulonglong2 wD = *(const ulonglong2*)&ws[k0 + kk][12];
                FMA2(accp[0], xk2, wA.x);  FMA2(accp[1], xk2, wA.y);
                FMA2(accp[2], xk2, wB.x);  FMA2(accp[3], xk2, wB.y);
                FMA2(accp[4], xk2, wC.x);  FMA2(accp[5], xk2, wC.y);
                FMA2(accp[6], xk2, wD.x);  FMA2(accp[7], xk2, wD.y);
            }
        }
        __syncthreads();
    }

    int row = row_base + rl;
    if (row < N_NODES) {
        float* op = h1 + (size_t)row * 16;
        #pragma unroll
        for (int q = 0; q < 4; q++) {
            float a, b, cc, d;
            asm("mov.b64 {%0, %1}, %2;" : "=f"(a), "=f"(b) : "l"(accp[q*2]));
            asm("mov.b64 {%0, %1}, %2;" : "=f"(cc), "=f"(d) : "l"(accp[q*2+1]));
            *(float4*)(op + q * 4) = make_float4(a, b, cc, d);
        }
    }
}

// ---------------------------------------------------------------------------
// CSR construction  (proven path)
// ---------------------------------------------------------------------------
__global__ void deg_kernel(const int* __restrict__ dst, int* __restrict__ deg) {
    int e = blockIdx.x * blockDim.x + threadIdx.x;
    if (e < N_EDGES) atomicAdd(&deg[dst[e]], 1);
}

__global__ __launch_bounds__(SCAN_BLK)
void scan1_kernel(const int* __restrict__ deg,
                  int* __restrict__ excl,
                  int* __restrict__ blksum) {
    __shared__ int wsum[32];
    int tid = threadIdx.x, lane = tid & 31, wid = tid >> 5;
    int i = blockIdx.x * SCAN_BLK + tid;
    int v = (i < N_NODES) ? deg[i] : 0;
    int x = v;
    #pragma unroll
    for (int d = 1; d < 32; d <<= 1) {
        int t = __shfl_up_sync(0xffffffffu, x, d);
        if (lane >= d) x += t;
    }
    if (lane == 31) wsum[wid] = x;
    __syncthreads();
    if (wid == 0) {
        int s = wsum[lane];
        #pragma unroll
        for (int d = 1; d < 32; d <<= 1) {
            int t = __shfl_up_sync(0xffffffffu, s, d);
            if (lane >= d) s += t;
        }
        wsum[lane] = s;
    }
    __syncthreads();
    int woff = (wid == 0) ? 0 : wsum[wid - 1];
    if (i < N_NODES) excl[i] = woff + x - v;
    if (tid == SCAN_BLK - 1) blksum[blockIdx.x] = wsum[31];
}

__global__ __launch_bounds__(128)
void scan2_kernel(int* __restrict__ blksum) {
    __shared__ int ws[4];
    int tid = threadIdx.x, lane = tid & 31, wid = tid >> 5;
    int v = (tid < NB_SCAN) ? blksum[tid] : 0;
    int x = v;
    #pragma unroll
    for (int d = 1; d < 32; d <<= 1) {
        int t = __shfl_up_sync(0xffffffffu, x, d);
        if (lane >= d) x += t;
    }
    if (lane == 31) ws[wid] = x;
    __syncthreads();
    int woff = 0;
    #pragma unroll
    for (int w = 0; w < 4; w++) if (w < wid) woff += ws[w];
    if (tid < NB_SCAN) blksum[tid] = woff + x - v;
}

__global__ void scan3_kernel(const int* __restrict__ excl,
                             const int* __restrict__ blksum,
                             int* __restrict__ rowptr,
                             int* __restrict__ cursor) {
    int i = blockIdx.x * blockDim.x + threadIdx.x;
    if (i >= N_NODES) return;
    int v = excl[i] + blksum[i / SCAN_BLK];
    rowptr[i] = v;
    cursor[i] = v;
    if (i == 0) rowptr[N_NODES] = N_EDGES;
}

__global__ void fill_kernel(const int* __restrict__ src,
                            const int* __restrict__ dst,
                            int* __restrict__ cursor,
                            int* __restrict__ csr_src) {
    int e = blockIdx.x * blockDim.x + threadIdx.x;
    if (e >= N_EDGES) return;
    int slot = atomicAdd(&cursor[dst[e]], 1);
    csr_src[slot] = src[e];
}

// ---------------------------------------------------------------------------
// Gather layer 1: 4 threads per node, float4 loads, csr indices deduped via
// group-masked width-4 shuffles.  (proven round-13 version)
// ---------------------------------------------------------------------------
__global__ void gather1_kernel(const float* __restrict__ h,
                               const int* __restrict__ rowptr,
                               const int* __restrict__ csr_src,
                               const float* __restrict__ bias,
                               float* __restrict__ out) {
    int t = blockIdx.x * blockDim.x + threadIdx.x;
    int nid = t >> 2;
    int c4  = t & 3;
    unsigned gmask = 0xFu << ((threadIdx.x & 31) & ~3);   // this 4-lane group
    if (nid >= N_NODES) return;
    int beg = rowptr[nid];
    int end = rowptr[nid + 1];
    const float4* hv = (const float4*)h;
    float4 s = make_float4(0.f, 0.f, 0.f, 0.f);
    int j = beg;
    for (; j + 4 <= end; j += 4) {
        int myi = csr_src[j + c4];
        int s0 = __shfl_sync(gmask, myi, 0, 4);
        int s1 = __shfl_sync(gmask, myi, 1, 4);
        int s2 = __shfl_sync(gmask, myi, 2, 4);
        int s3 = __shfl_sync(gmask, myi, 3, 4);
        float4 v0 = hv[(size_t)s0 * 4 + c4];
        float4 v1 = hv[(size_t)s1 * 4 + c4];
        float4 v2 = hv[(size_t)s2 * 4 + c4];
        float4 v3 = hv[(size_t)s3 * 4 + c4];
        s.x += (v0.x + v1.x) + (v2.x + v3.x);
        s.y += (v0.y + v1.y) + (v2.y + v3.y);
        s.z += (v0.z + v1.z) + (v2.z + v3.z);
        s.w += (v0.w + v1.w) + (v2.w + v3.w);
    }
    for (; j < end; j++) {
        float4 v = hv[(size_t)csr_src[j] * 4 + c4];
        s.x += v.x; s.y += v.y; s.z += v.z; s.w += v.w;
    }
    float inv = 1.f / fmaxf((float)(end - beg), 1.f);
    float4 m;
    m.x = s.x * inv; m.y = s.y * inv; m.z = s.z * inv; m.w = s.w * inv;
    float4 bb = __ldg(((const float4*)bias) + c4);
    m.x = fmaxf(m.x + bb.x, 0.f);
    m.y = fmaxf(m.y + bb.y, 0.f);
    m.z = fmaxf(m.z + bb.z, 0.f);
    m.w = fmaxf(m.w + bb.w, 0.f);
    ((float4*)out)[(size_t)nid * 4 + c4] = m;
}

// ---------------------------------------------------------------------------
// Fused gather2 + W2 matvec + log_softmax.  (proven round-13 version)
// ---------------------------------------------------------------------------
__global__ void gather2_out_kernel(const float* __restrict__ h,
                                   const int* __restrict__ rowptr,
                                   const int* __restrict__ csr_src,
                                   const float* __restrict__ W2,
                                   const float* __restrict__ b2,
                                   float* __restrict__ out) {
    __shared__ float w2s[HID * OUT_CH];
    __shared__ float b2s[OUT_CH];
    for (int i = threadIdx.x; i < HID * OUT_CH; i += blockDim.x) w2s[i] = W2[i];
    for (int i = threadIdx.x; i < OUT_CH;       i += blockDim.x) b2s[i] = b2[i];
    __syncthreads();

    int t = blockIdx.x * blockDim.x + threadIdx.x;
    int nid = t >> 2;
    int c4  = t & 3;
    unsigned gmask = 0xFu << ((threadIdx.x & 31) & ~3);   // this 4-lane group
    if (nid >= N_NODES) return;
    int beg = rowptr[nid];
    int end = rowptr[nid + 1];
    const float4* hv = (const float4*)h;
    float4 s = make_float4(0.f, 0.f, 0.f, 0.f);
    int j = beg;
    for (; j + 4 <= end; j += 4) {
        int myi = csr_src[j + c4];
        int s0 = __shfl_sync(gmask, myi, 0, 4);
        int s1 = __shfl_sync(gmask, myi, 1, 4);
        int s2 = __shfl_sync(gmask, myi, 2, 4);
        int s3 = __shfl_sync(gmask, myi, 3, 4);
        float4 v0 = hv[(size_t)s0 * 4 + c4];
        float4 v1 = hv[(size_t)s1 * 4 + c4];
        float4 v2 = hv[(size_t)s2 * 4 + c4];
        float4 v3 = hv[(size_t)s3 * 4 + c4];
        s.x += (v0.x + v1.x) + (v2.x + v3.x);
        s.y += (v0.y + v1.y) + (v2.y + v3.y);
        s.z += (v0.z + v1.z) + (v2.z + v3.z);
        s.w += (v0.w + v1.w) + (v2.w + v3.w);
    }
    for (; j < end; j++) {
        float4 v = hv[(size_t)csr_src[j] * 4 + c4];
        s.x += v.x; s.y += v.y; s.z += v.z; s.w += v.w;
    }
    float inv = 1.f / fmaxf((float)(end - beg), 1.f);
    float4 m;
    m.x = s.x * inv; m.y = s.y * inv; m.z = s.z * inv; m.w = s.w * inv;

    // share the 16 mean channels across the 4-lane group
    float ma[16];
    #pragma unroll
    for (int sl = 0; sl < 4; sl++) {
        ma[sl * 4 + 0] = __shfl_sync(gmask, m.x, sl, 4);
        ma[sl * 4 + 1] = __shfl_sync(gmask, m.y, sl, 4);
        ma[sl * 4 + 2] = __shfl_sync(gmask, m.z, sl, 4);
        ma[sl * 4 + 3] = __shfl_sync(gmask, m.w, sl, 4);
    }

    // each lane computes logits j = c4 + 4*i  (11 slots; last may be unused)
    float o[11];
    float lmax = -1e30f;
    int cnt = 0;
    for (int jj = c4; jj < OUT_CH; jj += 4, cnt++) {
        float v = b2s[jj];
        #pragma unroll
        for (int k = 0; k < HID; k++)
            v += ma[k] * w2s[k * OUT_CH + jj];
        o[cnt] = v;
        lmax = fmaxf(lmax, v);
    }
    // group reductions (xor 1, 2 stay inside the 4-lane group)
    lmax = fmaxf(lmax, __shfl_xor_sync(gmask, lmax, 1));
    lmax = fmaxf(lmax, __shfl_xor_sync(gmask, lmax, 2));
    float lsum = 0.f;
    for (int i = 0; i < cnt; i++) lsum += __expf(o[i] - lmax);
    lsum += __shfl_xor_sync(gmask, lsum, 1);
    lsum += __shfl_xor_sync(gmask, lsum, 2);
    float ls = __logf(lsum) + lmax;

    float* op = out + (size_t)nid * OUT_CH;
    int i = 0;
    for (int jj = c4; jj < OUT_CH; jj += 4, i++) op[jj] = o[i] - ls;
}

// ---------------------------------------------------------------------------
extern "C" void kernel_launch(void* const* d_in, const int* in_sizes, int n_in,
                              void* d_out, int out_size) {
    const float* x  = (const float*)d_in[0];
    const int*   ei = (const int*)  d_in[1];
    const float* W1 = (const float*)d_in[2];
    const float* b1 = (const float*)d_in[3];
    const float* W2 = (const float*)d_in[4];
    const float* b2 = (const float*)d_in[5];
    float* out = (float*)d_out;

    const int* src = ei;
    const int* dst = ei + N_EDGES;

    float *p_h1, *p_r;
    int *p_deg, *p_excl, *p_blksum, *p_rowptr, *p_cursor, *p_csr;
    cudaGetSymbolAddress((void**)&p_h1,     g_h1);
    cudaGetSymbolAddress((void**)&p_r,      g_r);
    cudaGetSymbolAddress((void**)&p_deg,    g_deg);
    cudaGetSymbolAddress((void**)&p_excl,   g_excl);
    cudaGetSymbolAddress((void**)&p_blksum, g_blksum);
    cudaGetSymbolAddress((void**)&p_rowptr, g_rowptr);
    cudaGetSymbolAddress((void**)&p_cursor, g_cursor);
    cudaGetSymbolAddress((void**)&p_csr,    g_csr);

    // Side stream + fork/join events (created on first call, which is the
    // uncaptured correctness run; reused identically during graph capture).
    static cudaStream_t s_csr = nullptr;
    static cudaEvent_t  ev_fork = nullptr, ev_join = nullptr;
    if (s_csr == nullptr) {
        cudaStreamCreateWithFlags(&s_csr, cudaStreamNonBlocking);
        cudaEventCreateWithFlags(&ev_fork, cudaEventDisableTiming);
        cudaEventCreateWithFlags(&ev_join, cudaEventDisableTiming);
    }

    // Fork: CSR chain on side stream, gemm on main stream — independent.
    cudaEventRecord(ev_fork, 0);
    cudaStreamWaitEvent(s_csr, ev_fork, 0);

    cudaMemsetAsync(p_deg, 0, sizeof(int) * N_NODES, s_csr);
    deg_kernel <<<(N_EDGES + 255) / 256, 256, 0, s_csr>>>(dst, p_deg);
    scan1_kernel<<<NB_SCAN, SCAN_BLK, 0, s_csr>>>(p_deg, p_excl, p_blksum);
    scan2_kernel<<<1, 128, 0, s_csr>>>(p_blksum);
    scan3_kernel<<<(N_NODES + 255) / 256, 256, 0, s_csr>>>(p_excl, p_blksum, p_rowptr, p_cursor);
    fill_kernel <<<(N_EDGES + 255) / 256, 256, 0, s_csr>>>(src, dst, p_cursor, p_csr);
    cudaEventRecord(ev_join, s_csr);

    // K1 on main stream, overlapped with CSR build
    gemm1_kernel<<<(N_NODES + M_TILE - 1) / M_TILE, 256>>>(x, W1, p_h1);

    // Join: gather1 needs both h1 and the CSR
    cudaStreamWaitEvent(0, ev_join, 0);

    gather1_kernel<<<(N_NODES * 4 + 255) / 256, 256>>>(p_h1, p_rowptr, p_csr, b1, p_r);
    gather2_out_kernel<<<(N_NODES * 4 + 255) / 256, 256>>>(p_r, p_rowptr, p_csr, W2, b2, out);
}